// round 5
// baseline (speedup 1.0000x reference)
#include <cuda_runtime.h>
#include <math.h>

#define C_IN   64
#define C_OUTD 32
#define V_N    2048
#define Q_N    512
#define BT_N   8
#define KSEL   103
#define JW     33            // 32 h-features + 1 (filt/w column)

// ---- scratch (static device globals; no runtime allocation) ----
__device__ float d_xl[BT_N * V_N * C_IN];        // 16.8 MB
__device__ float d_g [Q_N * KSEL * JW];          // 7 MB
__device__ int   d_ind[Q_N * KSEL];

__device__ __forceinline__ float wrap01(float d) {
    float t = d + 0.5f;
    t -= floorf(t);
    return t - 0.5f;
}

// ============================================================
// K0: xl[row, c] = x[row, :] @ W_lin[c, :] + b_lin[c]
// grid 4096 x 256; each block does 4 rows (256 outputs)
// ============================================================
__global__ void k_xlin(const float* __restrict__ x,
                       const float* __restrict__ Wl,
                       const float* __restrict__ bl) {
    __shared__ float xs[256];
    __shared__ float ws[64 * 65];   // transposed, padded to kill bank conflicts
    int tid = threadIdx.x;
    int base = blockIdx.x * 256;    // 4 rows * 64
    xs[tid] = x[base + tid];
    for (int idx = tid; idx < 4096; idx += 256) {
        int c = idx >> 6, i = idx & 63;
        ws[i * 65 + c] = Wl[idx];   // ws[i][c] = W_lin[c][i]
    }
    __syncthreads();
    int rl = tid >> 6, c = tid & 63;
    float acc = bl[c];
    const float* xr = &xs[rl * 64];
#pragma unroll
    for (int i = 0; i < 64; i++) acc += xr[i] * ws[i * 65 + c];
    d_xl[base + tid] = acc;
}

// ============================================================
// K1: per query (512 blocks, 256 threads)
//  - edist over 2048 candidates (wrapped torus distance)
//  - radix-select 103 smallest (exact kth value, ties by index)
//  - softmax weights over normalized e
//  - RFF -> W1 -> exact GELU -> g[q,k,j] = w_k * [h | 1]
// ============================================================
__global__ void k_select(const float* __restrict__ pos,
                         const float* __restrict__ qpos,
                         const float* __restrict__ Bmat,
                         const float* __restrict__ W1,
                         const float* __restrict__ b1) {
    __shared__ float e_s[V_N];
    __shared__ unsigned hist[256];
    __shared__ int   sel_i[KSEL];
    __shared__ float sel_e[KSEL];
    __shared__ float sel_w[KSEL];
    __shared__ float w1s[1024];
    __shared__ float bs[32], b1s[32];
    __shared__ unsigned s_kth;
    __shared__ int s_rem;
    __shared__ float s_min, s_sum;

    int q = blockIdx.x, tid = threadIdx.x;
    float q0 = __ldg(&qpos[2 * q]), q1 = __ldg(&qpos[2 * q + 1]);

    for (int i = tid; i < 1024; i += 256) w1s[i] = W1[i];
    if (tid < 32) { bs[tid] = Bmat[tid]; b1s[tid] = b1[tid]; }

    for (int v = tid; v < V_N; v += 256) {
        float d0 = wrap01(q0 - pos[2 * v]);
        float d1 = wrap01(q1 - pos[2 * v + 1]);
        e_s[v] = d0 * d0 + d1 * d1;
    }
    __syncthreads();

    // ---- radix select: exact value of the 103rd-smallest edist ----
    unsigned prefix = 0; int remaining = KSEL;
    for (int shift = 24; shift >= 0; shift -= 8) {
        for (int i = tid; i < 256; i += 256) hist[i] = 0;
        __syncthreads();
        unsigned pm = (shift == 24) ? 0u : (0xFFFFFFFFu << (shift + 8));
        for (int v = tid; v < V_N; v += 256) {
            unsigned u = __float_as_uint(e_s[v]);
            if ((u & pm) == prefix) atomicAdd(&hist[(u >> shift) & 255], 1u);
        }
        __syncthreads();
        if (tid == 0) {
            int rem = remaining; int b = 0;
            for (; b < 256; b++) { int c = (int)hist[b]; if (c >= rem) break; rem -= c; }
            s_kth = prefix | ((unsigned)b << shift);
            s_rem = rem;
        }
        __syncthreads();
        prefix = s_kth; remaining = s_rem;
        __syncthreads();
    }
    unsigned kth = prefix;

    // ---- deterministic collection (warp 0; ties taken in ascending index) ----
    if (tid < 32) {
        unsigned full = 0xffffffffu;
        unsigned ltm = (1u << tid) - 1u;
        int n = 0;
        for (int base = 0; base < V_N; base += 32) {
            int v = base + tid;
            unsigned u = __float_as_uint(e_s[v]);
            bool lt = u < kth;
            unsigned bal = __ballot_sync(full, lt);
            if (lt) { int p = n + __popc(bal & ltm); sel_i[p] = v; sel_e[p] = e_s[v]; }
            n += __popc(bal);
        }
        int ntot = n;
        for (int base = 0; base < V_N; base += 32) {
            int v = base + tid;
            unsigned u = __float_as_uint(e_s[v]);
            bool eq = (u == kth);
            unsigned bal = __ballot_sync(full, eq);
            if (eq) {
                int p = ntot + __popc(bal & ltm);
                if (p < KSEL) { sel_i[p] = v; sel_e[p] = e_s[v]; }
            }
            ntot += __popc(bal);
        }
    }
    __syncthreads();

    // ---- e normalization + softmax ----
    if (tid < 32) {
        float m = 3.0e38f;
        for (int k = tid; k < KSEL; k += 32) m = fminf(m, sel_e[k]);
        for (int o = 16; o; o >>= 1) m = fminf(m, __shfl_xor_sync(0xffffffffu, m, o));
        if (tid == 0) s_min = m;
    }
    __syncthreads();
    float emin = s_min;
    float emax = __uint_as_float(kth);           // max of selected set == kth value
    float denom = (emax - emin) + 1e-8f;
    if (tid < KSEL) sel_w[tid] = expf(-((sel_e[tid] - emin) / denom));
    __syncthreads();
    if (tid < 32) {
        float s = 0.f;
        for (int k = tid; k < KSEL; k += 32) s += sel_w[k];
        for (int o = 16; o; o >>= 1) s += __shfl_xor_sync(0xffffffffu, s, o);
        if (tid == 0) s_sum = s;
    }
    __syncthreads();

    // ---- per-k RFF -> MLP -> GELU -> g ----
    if (tid < KSEL) {
        float w = sel_w[tid] / s_sum;
        int v = sel_i[tid];
        float d0 = wrap01(q0 - pos[2 * v]);
        float d1 = wrap01(q1 - pos[2 * v + 1]);
        float kf[32];
#pragma unroll
        for (int j = 0; j < 16; j++) {
            float p = 6.283185307179586f * (d0 * bs[j] + d1 * bs[16 + j]);
            kf[j] = sinf(p);
            kf[16 + j] = cosf(p);
        }
        float* gq = &d_g[(q * KSEL + tid) * JW];
#pragma unroll 4
        for (int j2 = 0; j2 < 32; j2++) {
            float a = b1s[j2];
#pragma unroll
            for (int i = 0; i < 32; i++) a += kf[i] * w1s[j2 * 32 + i];
            float h = 0.5f * a * (1.0f + erff(a * 0.7071067811865475f));
            gq[j2] = w * h;
        }
        gq[32] = w;
        d_ind[q * KSEL + tid] = v;
    }
}

// ============================================================
// K2: per query (512 blocks, 256 threads, ~105 KB dyn smem)
// Phase 2 (per bt): gather xg (103x64 from L2), A = xg^T @ g (64x33)
// Phase 3: out[bt,d] = sum_{c,j} A[bt,c,j] * W~2[c*32+d, j] (+bias)
// ============================================================
#define GSZ 3400                // KSEL*33 = 3399, padded for float4 alignment
#define ASZ (BT_N * 64 * JW)    // 16896
#define SMEM_FLOATS (GSZ + ASZ + KSEL * 64)   // 26888 floats = 107552 B

__global__ void k_apply(const float* __restrict__ W2,
                        const float* __restrict__ filt,
                        const float* __restrict__ bias,
                        float* __restrict__ out) {
    extern __shared__ float sm[];
    float* g_s  = sm;             // [KSEL][33]
    float* A_s  = sm + GSZ;       // [8][64][33]
    float* xg_s = sm + GSZ + ASZ; // [KSEL][64]; reused as w2_s [128][33] in phase 3
    __shared__ int ind_s[KSEL];

    int q = blockIdx.x, tid = threadIdx.x;

    for (int i = tid; i < KSEL * JW; i += 256) g_s[i] = d_g[q * KSEL * JW + i];
    for (int i = tid; i < KSEL; i += 256)      ind_s[i] = d_ind[q * KSEL + i];
    __syncthreads();

    int tc = tid & 7;        // c block: 8 floats
    int tj = tid >> 3;       // j: 0..31

    for (int bt = 0; bt < BT_N; bt++) {
        // gather xg rows (each row 256B, coalesced; L2-resident)
        for (int i = tid; i < KSEL * 64; i += 256) {
            int r = i >> 6, c = i & 63;
            xg_s[i] = __ldg(&d_xl[((bt << 11) + ind_s[r]) * 64 + c]);
        }
        __syncthreads();

        float acc[8] = {0.f, 0.f, 0.f, 0.f, 0.f, 0.f, 0.f, 0.f};
#pragma unroll 4
        for (int k = 0; k < KSEL; k++) {
            float gv = g_s[k * JW + tj];
            const float4* xr = reinterpret_cast<const float4*>(&xg_s[k * 64 + tc * 8]);
            float4 a = xr[0], b = xr[1];
            acc[0] += a.x * gv; acc[1] += a.y * gv; acc[2] += a.z * gv; acc[3] += a.w * gv;
            acc[4] += b.x * gv; acc[5] += b.y * gv; acc[6] += b.z * gv; acc[7] += b.w * gv;
        }
#pragma unroll
        for (int i = 0; i < 8; i++)
            A_s[(bt * 64 + tc * 8 + i) * JW + tj] = acc[i];

        // j = 32 column: A0[c] = sum_k w_k * xg[k][c]
        if (tid < 64) {
            float a0 = 0.f;
#pragma unroll 4
            for (int k = 0; k < KSEL; k++) a0 += g_s[k * JW + 32] * xg_s[k * 64 + tid];
            A_s[(bt * 64 + tid) * JW + 32] = a0;
        }
        __syncthreads();
    }

    // ---- phase 3: contract A with W~2 = [W2 | filt] ----
    float* w2_s = xg_s;                  // overlay (4224 <= 6592 floats)
    int bt = tid >> 5, d = tid & 31;
    float o = 0.f;
    for (int ct = 0; ct < 16; ct++) {    // 4 c-values per tile -> 128 W2 rows
        for (int i = tid; i < 128 * JW; i += 256) {
            int r = i / JW, j = i - r * JW;
            int m = ct * 128 + r;
            w2_s[i] = (j < 32) ? __ldg(&W2[m * 32 + j]) : __ldg(&filt[m]);
        }
        __syncthreads();
#pragma unroll
        for (int cl = 0; cl < 4; cl++) {
            int c = ct * 4 + cl;
            const float* Ar = &A_s[(bt * 64 + c) * JW];
            const float* Wr = &w2_s[(cl * 32 + d) * JW];
#pragma unroll
            for (int j = 0; j < JW; j++) o += Ar[j] * Wr[j];
        }
        __syncthreads();
    }
    out[(bt * Q_N + q) * 32 + d] = o + bias[d];
}

// ============================================================
extern "C" void kernel_launch(void* const* d_in, const int* in_sizes, int n_in,
                              void* d_out, int out_size) {
    const float* x    = (const float*)d_in[0];
    const float* pos  = (const float*)d_in[1];
    const float* qpos = (const float*)d_in[2];
    const float* Wl   = (const float*)d_in[3];
    const float* bl   = (const float*)d_in[4];
    const float* Bm   = (const float*)d_in[5];
    const float* W1   = (const float*)d_in[6];
    const float* b1   = (const float*)d_in[7];
    const float* W2   = (const float*)d_in[8];
    const float* filt = (const float*)d_in[9];
    const float* bias = (const float*)d_in[10];
    float* out = (float*)d_out;

    cudaFuncSetAttribute(k_apply, cudaFuncAttributeMaxDynamicSharedMemorySize,
                         SMEM_FLOATS * (int)sizeof(float));

    k_xlin  <<<4096, 256>>>(x, Wl, bl);
    k_select<<<Q_N, 256>>>(pos, qpos, Bm, W1, b1);
    k_apply <<<Q_N, 256, SMEM_FLOATS * sizeof(float)>>>(W2, filt, bias, out);
}

// round 6
// speedup vs baseline: 1.3292x; 1.3292x over previous
#include <cuda_runtime.h>
#include <math.h>

#define C_IN   64
#define V_N    2048
#define Q_N    512
#define BT_N   8
#define KSEL   103
#define JW     33
#define M_TOT  2112          // 64 * 33

typedef unsigned long long ull;

// ---- scratch (static device globals; no runtime allocation) ----
__device__ float d_xl [BT_N * V_N * C_IN];     // 4.2 MB... (8*2048*64 floats)
__device__ float d_g  [Q_N * KSEL * JW];       // 7 MB
__device__ int   d_ind[Q_N * KSEL];
__device__ float d_A  [BT_N * Q_N * M_TOT];    // 34.6 MB
__device__ float d_W2e[M_TOT * 32];            // 270 KB

// ---- f32x2 packed math (FFMA2: only reachable via PTX) ----
__device__ __forceinline__ ull fma2v(ull a, ull b, ull c) {
    ull d; asm("fma.rn.f32x2 %0, %1, %2, %3;" : "=l"(d) : "l"(a), "l"(b), "l"(c)); return d;
}
__device__ __forceinline__ ull pack2(float lo, float hi) {
    ull r; asm("mov.b64 %0, {%1, %2};" : "=l"(r) : "f"(lo), "f"(hi)); return r;
}
__device__ __forceinline__ float2 unpack2(ull v) {
    float2 r; asm("mov.b64 {%0, %1}, %2;" : "=f"(r.x), "=f"(r.y) : "l"(v)); return r;
}
__device__ __forceinline__ float wrap01(float d) {
    float t = d + 0.5f; t -= floorf(t); return t - 0.5f;
}

// ============================================================
// K_w2e: d_W2e[(c*33+j)*32 + d] = W2[(c*32+d)*32 + j] (j<32) | filt[c*32+d] (j=32)
// ============================================================
__global__ void k_w2e(const float* __restrict__ W2, const float* __restrict__ filt) {
    int idx = blockIdx.x * 256 + threadIdx.x;
    if (idx < M_TOT * 32) {
        int m = idx >> 5, dd = idx & 31;
        int c = m / 33, j = m - c * 33;
        d_W2e[idx] = (j < 32) ? __ldg(&W2[(c * 32 + dd) * 32 + j]) : __ldg(&filt[c * 32 + dd]);
    }
}

// ============================================================
// K0: xl = x @ W_lin^T + b   (2048 blocks x 256; 8 rows/block; f32x2)
// ============================================================
__global__ void __launch_bounds__(256) k_xlin(const float* __restrict__ x,
                                              const float* __restrict__ Wl,
                                              const float* __restrict__ bl) {
    __shared__ __align__(16) float xs[512];
    __shared__ __align__(16) float ws[64 * 66];   // W row-major, padded stride 66
    int tid = threadIdx.x;
    int base = blockIdx.x * 512;
    xs[tid]       = x[base + tid];
    xs[tid + 256] = x[base + 256 + tid];
    for (int i = tid; i < 4096; i += 256) { int cc = i >> 6, ii = i & 63; ws[cc * 66 + ii] = Wl[i]; }
    __syncthreads();
    int c = tid & 63, rp = tid >> 6;
    ull aA = 0, aB = 0;
    const ull* wp = (const ull*)&ws[c * 66];
    const ull* xA = (const ull*)&xs[rp * 64];
    const ull* xB = (const ull*)&xs[(rp + 4) * 64];
#pragma unroll
    for (int i2 = 0; i2 < 32; i2++) {
        ull w2_ = wp[i2];
        aA = fma2v(xA[i2], w2_, aA);
        aB = fma2v(xB[i2], w2_, aB);
    }
    float bv = __ldg(&bl[c]);
    float2 fA = unpack2(aA), fB = unpack2(aB);
    d_xl[base + rp * 64 + c]       = fA.x + fA.y + bv;
    d_xl[base + (rp + 4) * 64 + c] = fB.x + fB.y + bv;
}

// ============================================================
// K1: per query — radix-select 103 NN, softmax weights, RFF/MLP/GELU -> g
// ============================================================
__global__ void __launch_bounds__(256) k_select(const float* __restrict__ pos,
                                                const float* __restrict__ qpos,
                                                const float* __restrict__ Bmat,
                                                const float* __restrict__ W1,
                                                const float* __restrict__ b1) {
    __shared__ float e_s[V_N];
    __shared__ unsigned hist[256];
    __shared__ int   sel_i[KSEL];
    __shared__ float sel_e[KSEL];
    __shared__ float sel_w[KSEL];
    __shared__ __align__(16) float kf_s[KSEL * 32];
    __shared__ float bs[32];
    __shared__ unsigned s_kth;
    __shared__ int s_rem;
    __shared__ float s_min, s_sum;
    __shared__ int w_lt[8], w_eq[8], w_lt_off[8], w_eq_off[8];

    int q = blockIdx.x, tid = threadIdx.x, wid = tid >> 5, lane = tid & 31;
    const unsigned full = 0xffffffffu;
    unsigned ltm = (1u << lane) - 1u;
    float q0 = __ldg(&qpos[2 * q]), q1 = __ldg(&qpos[2 * q + 1]);

    // W1 row for this lane, cached in registers as 16 f32 pairs
    ull wl[16];
#pragma unroll
    for (int t = 0; t < 16; t++) wl[t] = *(const ull*)&W1[lane * 32 + 2 * t];
    float b1r = __ldg(&b1[lane]);
    if (tid < 32) bs[tid] = __ldg(&Bmat[tid]);

    for (int v = tid; v < V_N; v += 256) {
        float d0 = wrap01(q0 - __ldg(&pos[2 * v]));
        float d1 = wrap01(q1 - __ldg(&pos[2 * v + 1]));
        e_s[v] = d0 * d0 + d1 * d1;
    }
    __syncthreads();

    // ---- radix select (4x8-bit passes, warp-parallel bucket scan) ----
    unsigned prefix = 0; int remaining = KSEL;
    for (int shift = 24; shift >= 0; shift -= 8) {
        hist[tid] = 0;
        __syncthreads();
        unsigned pm = (shift == 24) ? 0u : (0xFFFFFFFFu << (shift + 8));
        for (int v = tid; v < V_N; v += 256) {
            unsigned u = __float_as_uint(e_s[v]);
            if ((u & pm) == prefix) atomicAdd(&hist[(u >> shift) & 255], 1u);
        }
        __syncthreads();
        if (tid < 32) {
            unsigned c8[8]; int lsum = 0;
#pragma unroll
            for (int j = 0; j < 8; j++) { c8[j] = hist[tid * 8 + j]; lsum += (int)c8[j]; }
            int pre = lsum;
#pragma unroll
            for (int o = 1; o < 32; o <<= 1) { int t2 = __shfl_up_sync(full, pre, o); if (lane >= o) pre += t2; }
            int excl = pre - lsum;
            if (excl < remaining && pre >= remaining) {
                int r2 = remaining - excl; int cum = 0, j = 0;
#pragma unroll
                for (j = 0; j < 8; j++) { cum += (int)c8[j]; if (cum >= r2) break; }
                s_kth = prefix | ((unsigned)(tid * 8 + j) << shift);
                s_rem = r2 - (cum - (int)c8[j]);
            }
        }
        __syncthreads();
        prefix = s_kth; remaining = s_rem;
        __syncthreads();
    }
    unsigned kth = prefix;

    // ---- parallel collection across 8 warps (tie-break: ascending index) ----
    {
        int nlt = 0, neq = 0;
#pragma unroll
        for (int it = 0; it < 8; it++) {
            unsigned u = __float_as_uint(e_s[wid * 256 + it * 32 + lane]);
            nlt += __popc(__ballot_sync(full, u < kth));
            neq += __popc(__ballot_sync(full, u == kth));
        }
        if (lane == 0) { w_lt[wid] = nlt; w_eq[wid] = neq; }
        __syncthreads();
        if (tid == 0) {
            int a = 0;
            for (int w = 0; w < 8; w++) { w_lt_off[w] = a; a += w_lt[w]; }
            int b2 = a;
            for (int w = 0; w < 8; w++) { w_eq_off[w] = b2; b2 += w_eq[w]; }
        }
        __syncthreads();
        int plt = w_lt_off[wid], peq = w_eq_off[wid];
#pragma unroll
        for (int it = 0; it < 8; it++) {
            int v = wid * 256 + it * 32 + lane;
            unsigned u = __float_as_uint(e_s[v]);
            bool lt = u < kth; unsigned bal = __ballot_sync(full, lt);
            if (lt) { int p = plt + __popc(bal & ltm); sel_i[p] = v; sel_e[p] = e_s[v]; }
            plt += __popc(bal);
            bool eq = (u == kth); unsigned b3 = __ballot_sync(full, eq);
            if (eq) { int p = peq + __popc(b3 & ltm); if (p < KSEL) { sel_i[p] = v; sel_e[p] = e_s[v]; } }
            peq += __popc(b3);
        }
    }
    __syncthreads();

    // ---- e normalization + softmax ----
    if (tid < 32) {
        float m = 3.0e38f;
        for (int k = lane; k < KSEL; k += 32) m = fminf(m, sel_e[k]);
        for (int o = 16; o; o >>= 1) m = fminf(m, __shfl_xor_sync(full, m, o));
        if (lane == 0) s_min = m;
    }
    __syncthreads();
    float emin = s_min;
    float emax = __uint_as_float(kth);          // max of selected set == kth value
    float denom = (emax - emin) + 1e-8f;
    if (tid < KSEL) sel_w[tid] = expf(-((sel_e[tid] - emin) / denom));
    __syncthreads();
    if (tid < 32) {
        float s = 0.f;
        for (int k = lane; k < KSEL; k += 32) s += sel_w[k];
        for (int o = 16; o; o >>= 1) s += __shfl_xor_sync(full, s, o);
        if (lane == 0) s_sum = s;
    }
    __syncthreads();

    // ---- RFF features (103 threads), w / ind writeout ----
    if (tid < KSEL) {
        float w = sel_w[tid] / s_sum;
        sel_w[tid] = w;
        int v = sel_i[tid];
        float d0 = wrap01(q0 - __ldg(&pos[2 * v]));
        float d1 = wrap01(q1 - __ldg(&pos[2 * v + 1]));
#pragma unroll
        for (int j = 0; j < 16; j++) {
            float p = 6.283185307179586f * (d0 * bs[j] + d1 * bs[16 + j]);
            float sv, cv; sincosf(p, &sv, &cv);
            kf_s[tid * 32 + j]      = sv;
            kf_s[tid * 32 + 16 + j] = cv;
        }
        d_g[(q * KSEL + tid) * JW + 32] = w;
        d_ind[q * KSEL + tid] = v;
    }
    __syncthreads();

    // ---- MLP: all 256 threads; warp w handles k = w, w+8, ...; lane = j2 ----
#pragma unroll 1
    for (int rr = 0; rr < 13; rr++) {
        int k = wid + rr * 8;
        if (k < KSEL) {
            ull acc = 0;
            const ull* kp = (const ull*)&kf_s[k * 32];
#pragma unroll
            for (int t = 0; t < 16; t++) acc = fma2v(kp[t], wl[t], acc);
            float2 f = unpack2(acc);
            float a = f.x + f.y + b1r;
            float h = 0.5f * a * (1.0f + erff(a * 0.70710678118654752f));
            d_g[(q * KSEL + k) * JW + lane] = sel_w[k] * h;
        }
    }
}

// ============================================================
// K2a: per (q,bt): gather xg, A[c*33+j] = sum_k g[k,j]*xg[k,c]  (f32x2)
// ============================================================
__global__ void __launch_bounds__(256) k_gA() {
    __shared__ __align__(16) float g_s[KSEL * JW + 1];   // 3400
    __shared__ __align__(16) float xg_s[KSEL * C_IN];    // 6592
    __shared__ int ind_s[KSEL];

    int bx = blockIdx.x, q = bx >> 3, bt = bx & 7, tid = threadIdx.x;
    for (int i = tid; i < KSEL * JW; i += 256) g_s[i] = d_g[q * KSEL * JW + i];
    if (tid < KSEL) ind_s[tid] = d_ind[q * KSEL + tid];
    __syncthreads();

    // gather: prefetch indices into registers, then batched independent LDGs
    {
        int r = tid >> 6, c = tid & 63;
        int idxs[26];
#pragma unroll
        for (int u = 0; u < 26; u++) { int rr = r + u * 4; idxs[u] = (rr < KSEL) ? ind_s[rr] : 0; }
        const float* xbase = &d_xl[bt * V_N * C_IN];
#pragma unroll
        for (int u = 0; u < 26; u++) {
            int rr = r + u * 4;
            if (rr < KSEL) xg_s[rr * 64 + c] = __ldg(&xbase[idxs[u] * 64 + c]);
        }
    }
    __syncthreads();

    int tc = tid & 7, tj = tid >> 3;
    ull a0 = 0, a1 = 0, a2 = 0, a3 = 0;
#pragma unroll 2
    for (int k = 0; k < KSEL; k++) {
        float gv = g_s[k * JW + tj];
        ull gp = pack2(gv, gv);
        const ulonglong2* xp = (const ulonglong2*)&xg_s[k * 64 + tc * 8];
        ulonglong2 p0 = xp[0], p1 = xp[1];
        a0 = fma2v(p0.x, gp, a0); a1 = fma2v(p0.y, gp, a1);
        a2 = fma2v(p1.x, gp, a2); a3 = fma2v(p1.y, gp, a3);
    }

    float aw = 0.f;
    if (tid < 64) {
#pragma unroll 4
        for (int k = 0; k < KSEL; k++) aw += g_s[k * JW + 32] * xg_s[k * 64 + tid];
    }

    int row = bt * Q_N + q;
    float* Ar = &d_A[row * M_TOT];
    float2 f0 = unpack2(a0), f1 = unpack2(a1), f2 = unpack2(a2), f3 = unpack2(a3);
    int cb = tc * 8;
    Ar[(cb + 0) * JW + tj] = f0.x; Ar[(cb + 1) * JW + tj] = f0.y;
    Ar[(cb + 2) * JW + tj] = f1.x; Ar[(cb + 3) * JW + tj] = f1.y;
    Ar[(cb + 4) * JW + tj] = f2.x; Ar[(cb + 5) * JW + tj] = f2.y;
    Ar[(cb + 6) * JW + tj] = f3.x; Ar[(cb + 7) * JW + tj] = f3.y;
    if (tid < 64) Ar[tid * JW + 32] = aw;
}

// ============================================================
// K2b: out[row,d] = sum_m A[row,m] * W2e[m,d] + bias[d]
// 128 blocks x 256; 32 rows/block; m tiled by 264; f32x2
// ============================================================
#define MTI 264
#define WPD 266
__global__ void __launch_bounds__(256) k_gB(const float* __restrict__ bias,
                                            float* __restrict__ out) {
    extern __shared__ float sm2[];
    float* As = sm2;               // [32][264]
    float* Wt = sm2 + 32 * MTI;    // [32][266] transposed W2e tile
    int tid = threadIdx.x, wid = tid >> 5, lane = tid & 31;
    int r0 = blockIdx.x * 32;
    ull acc[4] = {0, 0, 0, 0};

    for (int t = 0; t < 8; t++) {
        int mbase = t * MTI;
#pragma unroll
        for (int rr2 = 0; rr2 < 4; rr2++) {
            int rloc = wid * 4 + rr2;
            const float* src = &d_A[(r0 + rloc) * M_TOT + mbase];
            for (int m = lane; m < MTI; m += 32) As[rloc * MTI + m] = src[m];
        }
        for (int i = tid; i < MTI * 32; i += 256) {
            int m = i >> 5, dd = i & 31;
            Wt[dd * WPD + m] = d_W2e[mbase * 32 + i];
        }
        __syncthreads();
#pragma unroll 4
        for (int mp = 0; mp < MTI / 2; mp++) {
            ull wp = *(const ull*)&Wt[lane * WPD + 2 * mp];
            acc[0] = fma2v(*(const ull*)&As[(wid * 4 + 0) * MTI + 2 * mp], wp, acc[0]);
            acc[1] = fma2v(*(const ull*)&As[(wid * 4 + 1) * MTI + 2 * mp], wp, acc[1]);
            acc[2] = fma2v(*(const ull*)&As[(wid * 4 + 2) * MTI + 2 * mp], wp, acc[2]);
            acc[3] = fma2v(*(const ull*)&As[(wid * 4 + 3) * MTI + 2 * mp], wp, acc[3]);
        }
        __syncthreads();
    }
    float bv = __ldg(&bias[lane]);
#pragma unroll
    for (int j = 0; j < 4; j++) {
        float2 f = unpack2(acc[j]);
        out[(r0 + wid * 4 + j) * 32 + lane] = f.x + f.y + bv;
    }
}

// ============================================================
extern "C" void kernel_launch(void* const* d_in, const int* in_sizes, int n_in,
                              void* d_out, int out_size) {
    const float* x    = (const float*)d_in[0];
    const float* pos  = (const float*)d_in[1];
    const float* qpos = (const float*)d_in[2];
    const float* Wl   = (const float*)d_in[3];
    const float* bl   = (const float*)d_in[4];
    const float* Bm   = (const float*)d_in[5];
    const float* W1   = (const float*)d_in[6];
    const float* b1   = (const float*)d_in[7];
    const float* W2   = (const float*)d_in[8];
    const float* filt = (const float*)d_in[9];
    const float* bias = (const float*)d_in[10];
    float* out = (float*)d_out;

    cudaFuncSetAttribute(k_gB, cudaFuncAttributeMaxDynamicSharedMemorySize,
                         (32 * MTI + 32 * WPD) * (int)sizeof(float));

    k_w2e  <<<264, 256>>>(W2, filt);
    k_xlin <<<2048, 256>>>(x, Wl, bl);
    k_select<<<Q_N, 256>>>(pos, qpos, Bm, W1, b1);
    k_gA   <<<Q_N * BT_N, 256>>>();
    k_gB   <<<128, 256, (32 * MTI + 32 * WPD) * sizeof(float)>>>(bias, out);
}

// round 7
// speedup vs baseline: 1.9469x; 1.4647x over previous
#include <cuda_runtime.h>
#include <math.h>

#define C_IN   64
#define V_N    2048
#define Q_N    512
#define BT_N   8
#define KSEL   103
#define JW     33
#define M_TOT  2112          // 64 * 33
#define GST    36            // padded g row stride (16B-aligned float4 at j*4)

typedef unsigned long long ull;

// ---- scratch (static device globals; no runtime allocation) ----
__device__ float d_xl [BT_N * V_N * C_IN];
__device__ float d_g  [Q_N * KSEL * JW];
__device__ int   d_ind[Q_N * KSEL];
__device__ float d_A  [BT_N * Q_N * M_TOT];    // layout: [row][j*64 + c]
__device__ float d_W2e[M_TOT * 32];            // [j*64+c][d]

// ---- f32x2 packed math (FFMA2: only reachable via PTX) ----
__device__ __forceinline__ ull fma2v(ull a, ull b, ull c) {
    ull d; asm("fma.rn.f32x2 %0, %1, %2, %3;" : "=l"(d) : "l"(a), "l"(b), "l"(c)); return d;
}
__device__ __forceinline__ ull pack2(float lo, float hi) {
    ull r; asm("mov.b64 %0, {%1, %2};" : "=l"(r) : "f"(lo), "f"(hi)); return r;
}
__device__ __forceinline__ float2 unpack2(ull v) {
    float2 r; asm("mov.b64 {%0, %1}, %2;" : "=f"(r.x), "=f"(r.y) : "l"(v)); return r;
}
__device__ __forceinline__ float wrap01(float d) {
    float t = d + 0.5f; t -= floorf(t); return t - 0.5f;
}

// ============================================================
// K_w2e: d_W2e[(j*64+c)*32 + d] = W2[(c*32+d)*32 + j] (j<32) | filt[c*32+d]
// ============================================================
__global__ void k_w2e(const float* __restrict__ W2, const float* __restrict__ filt) {
    int idx = blockIdx.x * 256 + threadIdx.x;
    if (idx < M_TOT * 32) {
        int m = idx >> 5, dd = idx & 31;
        int j = m >> 6, c = m & 63;
        d_W2e[idx] = (j < 32) ? __ldg(&W2[(c * 32 + dd) * 32 + j]) : __ldg(&filt[c * 32 + dd]);
    }
}

// ============================================================
// K0: xl = x @ W_lin^T + b
// ============================================================
__global__ void __launch_bounds__(256) k_xlin(const float* __restrict__ x,
                                              const float* __restrict__ Wl,
                                              const float* __restrict__ bl) {
    __shared__ __align__(16) float xs[512];
    __shared__ __align__(16) float ws[64 * 66];
    int tid = threadIdx.x;
    int base = blockIdx.x * 512;
    xs[tid]       = x[base + tid];
    xs[tid + 256] = x[base + 256 + tid];
    for (int i = tid; i < 4096; i += 256) { int cc = i >> 6, ii = i & 63; ws[cc * 66 + ii] = Wl[i]; }
    __syncthreads();
    int c = tid & 63, rp = tid >> 6;
    ull aA = 0, aB = 0;
    const ull* wp = (const ull*)&ws[c * 66];
    const ull* xA = (const ull*)&xs[rp * 64];
    const ull* xB = (const ull*)&xs[(rp + 4) * 64];
#pragma unroll
    for (int i2 = 0; i2 < 32; i2++) {
        ull w2_ = wp[i2];
        aA = fma2v(xA[i2], w2_, aA);
        aB = fma2v(xB[i2], w2_, aB);
    }
    float bv = __ldg(&bl[c]);
    float2 fA = unpack2(aA), fB = unpack2(aB);
    d_xl[base + rp * 64 + c]       = fA.x + fA.y + bv;
    d_xl[base + (rp + 4) * 64 + c] = fB.x + fB.y + bv;
}

// ============================================================
// K1: per query — radix-select 103 NN, softmax weights, RFF/MLP/GELU -> g
// ============================================================
__global__ void __launch_bounds__(256) k_select(const float* __restrict__ pos,
                                                const float* __restrict__ qpos,
                                                const float* __restrict__ Bmat,
                                                const float* __restrict__ W1,
                                                const float* __restrict__ b1) {
    __shared__ float e_s[V_N];
    __shared__ unsigned hist[256];
    __shared__ int   sel_i[KSEL];
    __shared__ float sel_e[KSEL];
    __shared__ float sel_w[KSEL];
    __shared__ __align__(16) float kf_s[KSEL * 32];
    __shared__ float bs[32];
    __shared__ unsigned s_kth;
    __shared__ int s_rem;
    __shared__ float s_min, s_sum;
    __shared__ int w_lt[8], w_eq[8], w_lt_off[8], w_eq_off[8];

    int q = blockIdx.x, tid = threadIdx.x, wid = tid >> 5, lane = tid & 31;
    const unsigned full = 0xffffffffu;
    unsigned ltm = (1u << lane) - 1u;
    float q0 = __ldg(&qpos[2 * q]), q1 = __ldg(&qpos[2 * q + 1]);

    ull wl[16];
#pragma unroll
    for (int t = 0; t < 16; t++) wl[t] = *(const ull*)&W1[lane * 32 + 2 * t];
    float b1r = __ldg(&b1[lane]);
    if (tid < 32) bs[tid] = __ldg(&Bmat[tid]);

    for (int v = tid; v < V_N; v += 256) {
        float d0 = wrap01(q0 - __ldg(&pos[2 * v]));
        float d1 = wrap01(q1 - __ldg(&pos[2 * v + 1]));
        e_s[v] = d0 * d0 + d1 * d1;
    }
    __syncthreads();

    unsigned prefix = 0; int remaining = KSEL;
    for (int shift = 24; shift >= 0; shift -= 8) {
        hist[tid] = 0;
        __syncthreads();
        unsigned pm = (shift == 24) ? 0u : (0xFFFFFFFFu << (shift + 8));
        for (int v = tid; v < V_N; v += 256) {
            unsigned u = __float_as_uint(e_s[v]);
            if ((u & pm) == prefix) atomicAdd(&hist[(u >> shift) & 255], 1u);
        }
        __syncthreads();
        if (tid < 32) {
            unsigned c8[8]; int lsum = 0;
#pragma unroll
            for (int j = 0; j < 8; j++) { c8[j] = hist[tid * 8 + j]; lsum += (int)c8[j]; }
            int pre = lsum;
#pragma unroll
            for (int o = 1; o < 32; o <<= 1) { int t2 = __shfl_up_sync(full, pre, o); if (lane >= o) pre += t2; }
            int excl = pre - lsum;
            if (excl < remaining && pre >= remaining) {
                int r2 = remaining - excl; int cum = 0, j = 0;
#pragma unroll
                for (j = 0; j < 8; j++) { cum += (int)c8[j]; if (cum >= r2) break; }
                s_kth = prefix | ((unsigned)(tid * 8 + j) << shift);
                s_rem = r2 - (cum - (int)c8[j]);
            }
        }
        __syncthreads();
        prefix = s_kth; remaining = s_rem;
        __syncthreads();
    }
    unsigned kth = prefix;

    {
        int nlt = 0, neq = 0;
#pragma unroll
        for (int it = 0; it < 8; it++) {
            unsigned u = __float_as_uint(e_s[wid * 256 + it * 32 + lane]);
            nlt += __popc(__ballot_sync(full, u < kth));
            neq += __popc(__ballot_sync(full, u == kth));
        }
        if (lane == 0) { w_lt[wid] = nlt; w_eq[wid] = neq; }
        __syncthreads();
        if (tid == 0) {
            int a = 0;
            for (int w = 0; w < 8; w++) { w_lt_off[w] = a; a += w_lt[w]; }
            int b2 = a;
            for (int w = 0; w < 8; w++) { w_eq_off[w] = b2; b2 += w_eq[w]; }
        }
        __syncthreads();
        int plt = w_lt_off[wid], peq = w_eq_off[wid];
#pragma unroll
        for (int it = 0; it < 8; it++) {
            int v = wid * 256 + it * 32 + lane;
            unsigned u = __float_as_uint(e_s[v]);
            bool lt = u < kth; unsigned bal = __ballot_sync(full, lt);
            if (lt) { int p = plt + __popc(bal & ltm); sel_i[p] = v; sel_e[p] = e_s[v]; }
            plt += __popc(bal);
            bool eq = (u == kth); unsigned b3 = __ballot_sync(full, eq);
            if (eq) { int p = peq + __popc(b3 & ltm); if (p < KSEL) { sel_i[p] = v; sel_e[p] = e_s[v]; } }
            peq += __popc(b3);
        }
    }
    __syncthreads();

    if (tid < 32) {
        float m = 3.0e38f;
        for (int k = lane; k < KSEL; k += 32) m = fminf(m, sel_e[k]);
        for (int o = 16; o; o >>= 1) m = fminf(m, __shfl_xor_sync(full, m, o));
        if (lane == 0) s_min = m;
    }
    __syncthreads();
    float emin = s_min;
    float emax = __uint_as_float(kth);
    float denom = (emax - emin) + 1e-8f;
    if (tid < KSEL) sel_w[tid] = expf(-((sel_e[tid] - emin) / denom));
    __syncthreads();
    if (tid < 32) {
        float s = 0.f;
        for (int k = lane; k < KSEL; k += 32) s += sel_w[k];
        for (int o = 16; o; o >>= 1) s += __shfl_xor_sync(full, s, o);
        if (lane == 0) s_sum = s;
    }
    __syncthreads();

    if (tid < KSEL) {
        float w = sel_w[tid] / s_sum;
        sel_w[tid] = w;
        int v = sel_i[tid];
        float d0 = wrap01(q0 - __ldg(&pos[2 * v]));
        float d1 = wrap01(q1 - __ldg(&pos[2 * v + 1]));
#pragma unroll
        for (int j = 0; j < 16; j++) {
            float p = 6.283185307179586f * (d0 * bs[j] + d1 * bs[16 + j]);
            float sv, cv; sincosf(p, &sv, &cv);
            kf_s[tid * 32 + j]      = sv;
            kf_s[tid * 32 + 16 + j] = cv;
        }
        d_g[(q * KSEL + tid) * JW + 32] = w;
        d_ind[q * KSEL + tid] = v;
    }
    __syncthreads();

#pragma unroll 1
    for (int rr = 0; rr < 13; rr++) {
        int k = wid + rr * 8;
        if (k < KSEL) {
            ull acc = 0;
            const ull* kp = (const ull*)&kf_s[k * 32];
#pragma unroll
            for (int t = 0; t < 16; t++) acc = fma2v(kp[t], wl[t], acc);
            float2 f = unpack2(acc);
            float a = f.x + f.y + b1r;
            float h = 0.5f * a * (1.0f + erff(a * 0.70710678118654752f));
            d_g[(q * KSEL + k) * JW + lane] = sel_w[k] * h;
        }
    }
}

// ============================================================
// K2a: block = (q, bt-pair), 128 threads (two 64-thread halves, one bt each).
// Thread tile: 8c x 4j  ->  48B LDS / 16 FFMA2 per k.
// A[row][j*64+c] = sum_k g[k,j]*xg[k,c]
// ============================================================
#define GA_SMEM ((KSEL * GST + 2 * KSEL * C_IN) * 4)   // 3708 + 13184 floats = 67568 B

__global__ void __launch_bounds__(128) k_gA() {
    extern __shared__ __align__(16) float sm[];
    float* g_s = sm;                       // [103][36]
    float* xg0 = sm + KSEL * GST;          // [103][64] bt0
    float* xg1 = xg0 + KSEL * C_IN;        // [103][64] bt1
    __shared__ int ind_s[KSEL];

    int bx = blockIdx.x, q = bx >> 2, btp = bx & 3;
    int tid = threadIdx.x;

    if (tid < KSEL) ind_s[tid] = d_ind[q * KSEL + tid];
    {
        const float* gsrc = &d_g[q * KSEL * JW];
        for (int i = tid; i < KSEL * JW; i += 128) {
            int k = i / 33, j = i - k * 33;
            g_s[k * GST + j] = gsrc[i];
        }
    }
    __syncthreads();

    int half = tid >> 6;       // 0/1 -> which bt of the pair
    int t = tid & 63;
    // gather: 64 threads per bt; 4 rows in flight x 16 float4 columns
    {
        const float* xb = &d_xl[(btp * 2 + half) * V_N * C_IN];
        float* xdst = half ? xg1 : xg0;
        int rr = t >> 4, c4 = (t & 15) * 4;
#pragma unroll 4
        for (int r = rr; r < KSEL; r += 4) {
            float4 v = __ldg((const float4*)&xb[ind_s[r] * C_IN + c4]);
            *(float4*)&xdst[r * C_IN + c4] = v;
        }
    }
    __syncthreads();

    int cg = t & 7, jg = t >> 3;           // cg: 8 c-groups of 8; jg: 8 j-groups of 4
    const float* xg = half ? xg1 : xg0;
    const float* xgp = &xg[cg * 8];
    const float* gsp = &g_s[jg * 4];

    ull acc[4][4];
#pragma unroll
    for (int a = 0; a < 4; a++)
#pragma unroll
        for (int b = 0; b < 4; b++) acc[a][b] = 0;

#pragma unroll 2
    for (int k = 0; k < KSEL; k++) {
        ulonglong2 x0 = *(const ulonglong2*)&xgp[k * C_IN];
        ulonglong2 x1 = *(const ulonglong2*)&xgp[k * C_IN + 4];
        float4 g4 = *(const float4*)&gsp[k * GST];
        ull gp0 = pack2(g4.x, g4.x), gp1 = pack2(g4.y, g4.y);
        ull gp2 = pack2(g4.z, g4.z), gp3 = pack2(g4.w, g4.w);
        acc[0][0] = fma2v(x0.x, gp0, acc[0][0]); acc[0][1] = fma2v(x0.y, gp0, acc[0][1]);
        acc[0][2] = fma2v(x1.x, gp0, acc[0][2]); acc[0][3] = fma2v(x1.y, gp0, acc[0][3]);
        acc[1][0] = fma2v(x0.x, gp1, acc[1][0]); acc[1][1] = fma2v(x0.y, gp1, acc[1][1]);
        acc[1][2] = fma2v(x1.x, gp1, acc[1][2]); acc[1][3] = fma2v(x1.y, gp1, acc[1][3]);
        acc[2][0] = fma2v(x0.x, gp2, acc[2][0]); acc[2][1] = fma2v(x0.y, gp2, acc[2][1]);
        acc[2][2] = fma2v(x1.x, gp2, acc[2][2]); acc[2][3] = fma2v(x1.y, gp2, acc[2][3]);
        acc[3][0] = fma2v(x0.x, gp3, acc[3][0]); acc[3][1] = fma2v(x0.y, gp3, acc[3][1]);
        acc[3][2] = fma2v(x1.x, gp3, acc[3][2]); acc[3][3] = fma2v(x1.y, gp3, acc[3][3]);
    }

    int row = (btp * 2 + half) * Q_N + q;
    float* Ar = &d_A[row * M_TOT];
#pragma unroll
    for (int j2 = 0; j2 < 4; j2++) {
        int off = (jg * 4 + j2) * C_IN + cg * 8;
        *(ulonglong2*)&Ar[off]     = make_ulonglong2(acc[j2][0], acc[j2][1]);
        *(ulonglong2*)&Ar[off + 4] = make_ulonglong2(acc[j2][2], acc[j2][3]);
    }
    // j = 32 column (weight column): A[32*64 + c] = sum_k w_k * xg[k][c]
    {
        float aw = 0.f;
#pragma unroll 4
        for (int k = 0; k < KSEL; k++) aw += g_s[k * GST + 32] * xg[k * C_IN + t];
        Ar[32 * C_IN + t] = aw;
    }
}

// ============================================================
// K2b: out[row,d] = sum_m A[row,m] * W2e[m,d] + bias[d]
// ============================================================
#define MTI 264
#define WPD 266
__global__ void __launch_bounds__(256) k_gB(const float* __restrict__ bias,
                                            float* __restrict__ out) {
    extern __shared__ float sm2[];
    float* As = sm2;               // [32][264]
    float* Wt = sm2 + 32 * MTI;    // [32][266]
    int tid = threadIdx.x, wid = tid >> 5, lane = tid & 31;
    int r0 = blockIdx.x * 32;
    ull acc[4] = {0, 0, 0, 0};

    for (int t = 0; t < 8; t++) {
        int mbase = t * MTI;
#pragma unroll
        for (int rr2 = 0; rr2 < 4; rr2++) {
            int rloc = wid * 4 + rr2;
            const float* src = &d_A[(r0 + rloc) * M_TOT + mbase];
            for (int m = lane; m < MTI; m += 32) As[rloc * MTI + m] = src[m];
        }
        for (int i = tid; i < MTI * 32; i += 256) {
            int m = i >> 5, dd = i & 31;
            Wt[dd * WPD + m] = d_W2e[mbase * 32 + i];
        }
        __syncthreads();
#pragma unroll 4
        for (int mp = 0; mp < MTI / 2; mp++) {
            ull wp = *(const ull*)&Wt[lane * WPD + 2 * mp];
            acc[0] = fma2v(*(const ull*)&As[(wid * 4 + 0) * MTI + 2 * mp], wp, acc[0]);
            acc[1] = fma2v(*(const ull*)&As[(wid * 4 + 1) * MTI + 2 * mp], wp, acc[1]);
            acc[2] = fma2v(*(const ull*)&As[(wid * 4 + 2) * MTI + 2 * mp], wp, acc[2]);
            acc[3] = fma2v(*(const ull*)&As[(wid * 4 + 3) * MTI + 2 * mp], wp, acc[3]);
        }
        __syncthreads();
    }
    float bv = __ldg(&bias[lane]);
#pragma unroll
    for (int j = 0; j < 4; j++) {
        float2 f = unpack2(acc[j]);
        out[(r0 + wid * 4 + j) * 32 + lane] = f.x + f.y + bv;
    }
}

// ============================================================
extern "C" void kernel_launch(void* const* d_in, const int* in_sizes, int n_in,
                              void* d_out, int out_size) {
    const float* x    = (const float*)d_in[0];
    const float* pos  = (const float*)d_in[1];
    const float* qpos = (const float*)d_in[2];
    const float* Wl   = (const float*)d_in[3];
    const float* bl   = (const float*)d_in[4];
    const float* Bm   = (const float*)d_in[5];
    const float* W1   = (const float*)d_in[6];
    const float* b1   = (const float*)d_in[7];
    const float* W2   = (const float*)d_in[8];
    const float* filt = (const float*)d_in[9];
    const float* bias = (const float*)d_in[10];
    float* out = (float*)d_out;

    cudaFuncSetAttribute(k_gA, cudaFuncAttributeMaxDynamicSharedMemorySize, GA_SMEM);
    cudaFuncSetAttribute(k_gB, cudaFuncAttributeMaxDynamicSharedMemorySize,
                         (32 * MTI + 32 * WPD) * (int)sizeof(float));

    k_w2e  <<<264, 256>>>(W2, filt);
    k_xlin <<<2048, 256>>>(x, Wl, bl);
    k_select<<<Q_N, 256>>>(pos, qpos, Bm, W1, b1);
    k_gA   <<<Q_N * 4, 128, GA_SMEM>>>();
    k_gB   <<<128, 256, (32 * MTI + 32 * WPD) * sizeof(float)>>>(bias, out);
}

// round 9
// speedup vs baseline: 2.0820x; 1.0694x over previous
#include <cuda_runtime.h>
#include <math.h>

#define C_IN   64
#define V_N    2048
#define Q_N    512
#define BT_N   8
#define KSEL   103
#define JW     33
#define M_TOT  2112          // 64 * 33
#define GST    36            // padded g row stride
#define RST    36            // reduction buffer row stride (16B-aligned: 36*4=144)

typedef unsigned long long ull;

// ---- scratch (static device globals; no runtime allocation) ----
__device__ float d_xl [BT_N * V_N * C_IN];
__device__ float d_g  [Q_N * KSEL * JW];
__device__ int   d_ind[Q_N * KSEL];
__device__ float d_A  [BT_N * Q_N * M_TOT];    // layout: [row][j*64 + c]
__device__ float d_W2e[M_TOT * 32];            // [j*64+c][d]

// ---- f32x2 packed math ----
__device__ __forceinline__ ull fma2v(ull a, ull b, ull c) {
    ull d; asm("fma.rn.f32x2 %0, %1, %2, %3;" : "=l"(d) : "l"(a), "l"(b), "l"(c)); return d;
}
__device__ __forceinline__ ull pack2(float lo, float hi) {
    ull r; asm("mov.b64 %0, {%1, %2};" : "=l"(r) : "f"(lo), "f"(hi)); return r;
}
__device__ __forceinline__ float2 unpack2(ull v) {
    float2 r; asm("mov.b64 {%0, %1}, %2;" : "=f"(r.x), "=f"(r.y) : "l"(v)); return r;
}
__device__ __forceinline__ float wrap01(float d) {
    float t = d + 0.5f; t -= floorf(t); return t - 0.5f;
}

// ============================================================
// K_w2e
// ============================================================
__global__ void k_w2e(const float* __restrict__ W2, const float* __restrict__ filt) {
    int idx = blockIdx.x * 256 + threadIdx.x;
    if (idx < M_TOT * 32) {
        int m = idx >> 5, dd = idx & 31;
        int j = m >> 6, c = m & 63;
        d_W2e[idx] = (j < 32) ? __ldg(&W2[(c * 32 + dd) * 32 + j]) : __ldg(&filt[c * 32 + dd]);
    }
}

// ============================================================
// K0: xl = x @ W_lin^T + b
// ============================================================
__global__ void __launch_bounds__(256) k_xlin(const float* __restrict__ x,
                                              const float* __restrict__ Wl,
                                              const float* __restrict__ bl) {
    __shared__ __align__(16) float xs[512];
    __shared__ __align__(16) float ws[64 * 66];
    int tid = threadIdx.x;
    int base = blockIdx.x * 512;
    xs[tid]       = x[base + tid];
    xs[tid + 256] = x[base + 256 + tid];
    for (int i = tid; i < 4096; i += 256) { int cc = i >> 6, ii = i & 63; ws[cc * 66 + ii] = Wl[i]; }
    __syncthreads();
    int c = tid & 63, rp = tid >> 6;
    ull aA = 0, aB = 0;
    const ull* wp = (const ull*)&ws[c * 66];
    const ull* xA = (const ull*)&xs[rp * 64];
    const ull* xB = (const ull*)&xs[(rp + 4) * 64];
#pragma unroll
    for (int i2 = 0; i2 < 32; i2++) {
        ull w2_ = wp[i2];
        aA = fma2v(xA[i2], w2_, aA);
        aB = fma2v(xB[i2], w2_, aB);
    }
    float bv = __ldg(&bl[c]);
    float2 fA = unpack2(aA), fB = unpack2(aB);
    d_xl[base + rp * 64 + c]       = fA.x + fA.y + bv;
    d_xl[base + (rp + 4) * 64 + c] = fB.x + fB.y + bv;
}

// ============================================================
// K1: per query — radix-select 103 NN, softmax weights, RFF/MLP/GELU -> g
// ============================================================
__global__ void __launch_bounds__(256) k_select(const float* __restrict__ pos,
                                                const float* __restrict__ qpos,
                                                const float* __restrict__ Bmat,
                                                const float* __restrict__ W1,
                                                const float* __restrict__ b1) {
    __shared__ float e_s[V_N];
    __shared__ unsigned hist[256];
    __shared__ int   sel_i[KSEL];
    __shared__ float sel_e[KSEL];
    __shared__ float sel_w[KSEL];
    __shared__ __align__(16) float kf_s[KSEL * 32];
    __shared__ float bs[32];
    __shared__ unsigned s_kth;
    __shared__ int s_rem;
    __shared__ float s_min, s_sum;
    __shared__ int w_lt[8], w_eq[8], w_lt_off[8], w_eq_off[8];

    int q = blockIdx.x, tid = threadIdx.x, wid = tid >> 5, lane = tid & 31;
    const unsigned full = 0xffffffffu;
    unsigned ltm = (1u << lane) - 1u;
    float q0 = __ldg(&qpos[2 * q]), q1 = __ldg(&qpos[2 * q + 1]);

    ull wl[16];
#pragma unroll
    for (int t = 0; t < 16; t++) wl[t] = *(const ull*)&W1[lane * 32 + 2 * t];
    float b1r = __ldg(&b1[lane]);
    if (tid < 32) bs[tid] = __ldg(&Bmat[tid]);

    for (int v = tid; v < V_N; v += 256) {
        float d0 = wrap01(q0 - __ldg(&pos[2 * v]));
        float d1 = wrap01(q1 - __ldg(&pos[2 * v + 1]));
        e_s[v] = d0 * d0 + d1 * d1;
    }
    __syncthreads();

    unsigned prefix = 0; int remaining = KSEL;
    for (int shift = 24; shift >= 0; shift -= 8) {
        hist[tid] = 0;
        __syncthreads();
        unsigned pm = (shift == 24) ? 0u : (0xFFFFFFFFu << (shift + 8));
        for (int v = tid; v < V_N; v += 256) {
            unsigned u = __float_as_uint(e_s[v]);
            if ((u & pm) == prefix) atomicAdd(&hist[(u >> shift) & 255], 1u);
        }
        __syncthreads();
        if (tid < 32) {
            unsigned c8[8]; int lsum = 0;
#pragma unroll
            for (int j = 0; j < 8; j++) { c8[j] = hist[tid * 8 + j]; lsum += (int)c8[j]; }
            int pre = lsum;
#pragma unroll
            for (int o = 1; o < 32; o <<= 1) { int t2 = __shfl_up_sync(full, pre, o); if (lane >= o) pre += t2; }
            int excl = pre - lsum;
            if (excl < remaining && pre >= remaining) {
                int r2 = remaining - excl; int cum = 0, j = 0;
#pragma unroll
                for (j = 0; j < 8; j++) { cum += (int)c8[j]; if (cum >= r2) break; }
                s_kth = prefix | ((unsigned)(tid * 8 + j) << shift);
                s_rem = r2 - (cum - (int)c8[j]);
            }
        }
        __syncthreads();
        prefix = s_kth; remaining = s_rem;
        __syncthreads();
    }
    unsigned kth = prefix;

    {
        int nlt = 0, neq = 0;
#pragma unroll
        for (int it = 0; it < 8; it++) {
            unsigned u = __float_as_uint(e_s[wid * 256 + it * 32 + lane]);
            nlt += __popc(__ballot_sync(full, u < kth));
            neq += __popc(__ballot_sync(full, u == kth));
        }
        if (lane == 0) { w_lt[wid] = nlt; w_eq[wid] = neq; }
        __syncthreads();
        if (tid == 0) {
            int a = 0;
            for (int w = 0; w < 8; w++) { w_lt_off[w] = a; a += w_lt[w]; }
            int b2 = a;
            for (int w = 0; w < 8; w++) { w_eq_off[w] = b2; b2 += w_eq[w]; }
        }
        __syncthreads();
        int plt = w_lt_off[wid], peq = w_eq_off[wid];
#pragma unroll
        for (int it = 0; it < 8; it++) {
            int v = wid * 256 + it * 32 + lane;
            unsigned u = __float_as_uint(e_s[v]);
            bool lt = u < kth; unsigned bal = __ballot_sync(full, lt);
            if (lt) { int p = plt + __popc(bal & ltm); sel_i[p] = v; sel_e[p] = e_s[v]; }
            plt += __popc(bal);
            bool eq = (u == kth); unsigned b3 = __ballot_sync(full, eq);
            if (eq) { int p = peq + __popc(b3 & ltm); if (p < KSEL) { sel_i[p] = v; sel_e[p] = e_s[v]; } }
            peq += __popc(b3);
        }
    }
    __syncthreads();

    if (tid < 32) {
        float m = 3.0e38f;
        for (int k = lane; k < KSEL; k += 32) m = fminf(m, sel_e[k]);
        for (int o = 16; o; o >>= 1) m = fminf(m, __shfl_xor_sync(full, m, o));
        if (lane == 0) s_min = m;
    }
    __syncthreads();
    float emin = s_min;
    float emax = __uint_as_float(kth);
    float denom = (emax - emin) + 1e-8f;
    if (tid < KSEL) sel_w[tid] = expf(-((sel_e[tid] - emin) / denom));
    __syncthreads();
    if (tid < 32) {
        float s = 0.f;
        for (int k = lane; k < KSEL; k += 32) s += sel_w[k];
        for (int o = 16; o; o >>= 1) s += __shfl_xor_sync(full, s, o);
        if (lane == 0) s_sum = s;
    }
    __syncthreads();

    if (tid < KSEL) {
        float w = sel_w[tid] / s_sum;
        sel_w[tid] = w;
        int v = sel_i[tid];
        float d0 = wrap01(q0 - __ldg(&pos[2 * v]));
        float d1 = wrap01(q1 - __ldg(&pos[2 * v + 1]));
#pragma unroll
        for (int j = 0; j < 16; j++) {
            float p = 6.283185307179586f * (d0 * bs[j] + d1 * bs[16 + j]);
            float sv, cv; sincosf(p, &sv, &cv);
            kf_s[tid * 32 + j]      = sv;
            kf_s[tid * 32 + 16 + j] = cv;
        }
        d_g[(q * KSEL + tid) * JW + 32] = w;
        d_ind[q * KSEL + tid] = v;
    }
    __syncthreads();

#pragma unroll 1
    for (int rr = 0; rr < 13; rr++) {
        int k = wid + rr * 8;
        if (k < KSEL) {
            ull acc = 0;
            const ull* kp = (const ull*)&kf_s[k * 32];
#pragma unroll
            for (int t = 0; t < 16; t++) acc = fma2v(kp[t], wl[t], acc);
            float2 f = unpack2(acc);
            float a = f.x + f.y + b1r;
            float h = 0.5f * a * (1.0f + erff(a * 0.70710678118654752f));
            d_g[(q * KSEL + k) * JW + lane] = sel_w[k] * h;
        }
    }
}

// ============================================================
// K2a: block = (q, bt-pair), 256 threads.
// Thread = (kh, bt-half, t): kh splits k-range in two; 8c x 4j tile.
// Final cross-kh reduction through smem (overlaid on xg0, stride 36).
// ============================================================
#define GA_SMEM ((KSEL * GST + 2 * KSEL * C_IN) * 4)   // 67568 B

__global__ void __launch_bounds__(256, 3) k_gA() {
    extern __shared__ __align__(16) float sm[];
    float* g_s = sm;                       // [103][36]
    float* xg0 = sm + KSEL * GST;          // [103][64] bt0
    float* xg1 = xg0 + KSEL * C_IN;        // [103][64] bt1
    __shared__ int ind_s[KSEL];

    int bx = blockIdx.x, q = bx >> 2, btp = bx & 3;
    int tid = threadIdx.x;

    if (tid < KSEL) ind_s[tid] = d_ind[q * KSEL + tid];
    {
        const float* gsrc = &d_g[q * KSEL * JW];
        for (int i = tid; i < KSEL * JW; i += 256) {
            int k = i / 33, j = i - k * 33;
            g_s[k * GST + j] = gsrc[i];
        }
    }
    __syncthreads();

    // gather: 128 threads per bt, 8 rows in flight x 16 float4 columns
    {
        int gb = tid >> 7;
        int gt = tid & 127;
        const float* xb = &d_xl[(btp * 2 + gb) * V_N * C_IN];
        float* xdst = gb ? xg1 : xg0;
        int rr = gt >> 4, c4 = (gt & 15) * 4;
#pragma unroll 4
        for (int r = rr; r < KSEL; r += 8) {
            float4 v = __ldg((const float4*)&xb[ind_s[r] * C_IN + c4]);
            *(float4*)&xdst[r * C_IN + c4] = v;
        }
    }
    __syncthreads();

    int kh   = tid >> 7;                   // k-half: 0 -> [0,52), 1 -> [52,103)
    int half = (tid >> 6) & 1;             // bt of pair
    int t    = tid & 63;
    int cg = t & 7, jg = t >> 3;
    const float* xg = half ? xg1 : xg0;
    const float* xgp = &xg[cg * 8];
    const float* gsp = &g_s[jg * 4];
    int kbeg = kh ? 52 : 0;
    int kend = kh ? KSEL : 52;

    ull acc[4][4];
#pragma unroll
    for (int a = 0; a < 4; a++)
#pragma unroll
        for (int b = 0; b < 4; b++) acc[a][b] = 0;

#pragma unroll 2
    for (int k = kbeg; k < kend; k++) {
        ulonglong2 x0 = *(const ulonglong2*)&xgp[k * C_IN];
        ulonglong2 x1 = *(const ulonglong2*)&xgp[k * C_IN + 4];
        float4 g4 = *(const float4*)&gsp[k * GST];
        ull gp0 = pack2(g4.x, g4.x), gp1 = pack2(g4.y, g4.y);
        ull gp2 = pack2(g4.z, g4.z), gp3 = pack2(g4.w, g4.w);
        acc[0][0] = fma2v(x0.x, gp0, acc[0][0]); acc[0][1] = fma2v(x0.y, gp0, acc[0][1]);
        acc[0][2] = fma2v(x1.x, gp0, acc[0][2]); acc[0][3] = fma2v(x1.y, gp0, acc[0][3]);
        acc[1][0] = fma2v(x0.x, gp1, acc[1][0]); acc[1][1] = fma2v(x0.y, gp1, acc[1][1]);
        acc[1][2] = fma2v(x1.x, gp1, acc[1][2]); acc[1][3] = fma2v(x1.y, gp1, acc[1][3]);
        acc[2][0] = fma2v(x0.x, gp2, acc[2][0]); acc[2][1] = fma2v(x0.y, gp2, acc[2][1]);
        acc[2][2] = fma2v(x1.x, gp2, acc[2][2]); acc[2][3] = fma2v(x1.y, gp2, acc[2][3]);
        acc[3][0] = fma2v(x0.x, gp3, acc[3][0]); acc[3][1] = fma2v(x0.y, gp3, acc[3][1]);
        acc[3][2] = fma2v(x1.x, gp3, acc[3][2]); acc[3][3] = fma2v(x1.y, gp3, acc[3][3]);
    }

    // j = 32 (weight column) partial
    float aw = 0.f;
#pragma unroll 4
    for (int k = kbeg; k < kend; k++) aw += g_s[k * GST + 32] * xg[k * C_IN + t];

    __syncthreads();
    // kh==1 threads deposit partials into buffer overlaid on xg0 (stride 36 = 144B, 16B-aligned)
    float* red = xg0;                      // [128][RST]
    if (kh == 1) {
        float* rp = &red[(half * 64 + t) * RST];
#pragma unroll
        for (int j2 = 0; j2 < 4; j2++) {
            *(ulonglong2*)&rp[j2 * 8]     = make_ulonglong2(acc[j2][0], acc[j2][1]);
            *(ulonglong2*)&rp[j2 * 8 + 4] = make_ulonglong2(acc[j2][2], acc[j2][3]);
        }
        rp[32] = aw;
    }
    __syncthreads();
    if (kh == 0) {
        const float* rp = &red[(half * 64 + t) * RST];
        int row = (btp * 2 + half) * Q_N + q;
        float* Ar = &d_A[row * M_TOT];
#pragma unroll
        for (int j2 = 0; j2 < 4; j2++) {
            float2 f0 = unpack2(acc[j2][0]), f1 = unpack2(acc[j2][1]);
            float2 f2 = unpack2(acc[j2][2]), f3 = unpack2(acc[j2][3]);
            float4 p0 = *(const float4*)&rp[j2 * 8];
            float4 p1 = *(const float4*)&rp[j2 * 8 + 4];
            float4 o0 = make_float4(f0.x + p0.x, f0.y + p0.y, f1.x + p0.z, f1.y + p0.w);
            float4 o1 = make_float4(f2.x + p1.x, f2.y + p1.y, f3.x + p1.z, f3.y + p1.w);
            int off = (jg * 4 + j2) * C_IN + cg * 8;
            *(float4*)&Ar[off]     = o0;
            *(float4*)&Ar[off + 4] = o1;
        }
        Ar[32 * C_IN + t] = aw + rp[32];
    }
}

// ============================================================
// K2b: out[row,d] = sum_m A[row,m] * W2e[m,d] + bias[d]
// ============================================================
#define MTI 264
#define WPD 266
__global__ void __launch_bounds__(256) k_gB(const float* __restrict__ bias,
                                            float* __restrict__ out) {
    extern __shared__ float sm2[];
    float* As = sm2;               // [32][264]
    float* Wt = sm2 + 32 * MTI;    // [32][266]
    int tid = threadIdx.x, wid = tid >> 5, lane = tid & 31;
    int r0 = blockIdx.x * 32;
    ull acc[4] = {0, 0, 0, 0};

    for (int t = 0; t < 8; t++) {
        int mbase = t * MTI;
#pragma unroll
        for (int rr2 = 0; rr2 < 4; rr2++) {
            int rloc = wid * 4 + rr2;
            const float* src = &d_A[(r0 + rloc) * M_TOT + mbase];
            for (int m = lane; m < MTI; m += 32) As[rloc * MTI + m] = src[m];
        }
        for (int i = tid; i < MTI * 32; i += 256) {
            int m = i >> 5, dd = i & 31;
            Wt[dd * WPD + m] = d_W2e[mbase * 32 + i];
        }
        __syncthreads();
#pragma unroll 4
        for (int mp = 0; mp < MTI / 2; mp++) {
            ull wp = *(const ull*)&Wt[lane * WPD + 2 * mp];
            acc[0] = fma2v(*(const ull*)&As[(wid * 4 + 0) * MTI + 2 * mp], wp, acc[0]);
            acc[1] = fma2v(*(const ull*)&As[(wid * 4 + 1) * MTI + 2 * mp], wp, acc[1]);
            acc[2] = fma2v(*(const ull*)&As[(wid * 4 + 2) * MTI + 2 * mp], wp, acc[2]);
            acc[3] = fma2v(*(const ull*)&As[(wid * 4 + 3) * MTI + 2 * mp], wp, acc[3]);
        }
        __syncthreads();
    }
    float bv = __ldg(&bias[lane]);
#pragma unroll
    for (int j = 0; j < 4; j++) {
        float2 f = unpack2(acc[j]);
        out[(r0 + wid * 4 + j) * 32 + lane] = f.x + f.y + bv;
    }
}

// ============================================================
extern "C" void kernel_launch(void* const* d_in, const int* in_sizes, int n_in,
                              void* d_out, int out_size) {
    const float* x    = (const float*)d_in[0];
    const float* pos  = (const float*)d_in[1];
    const float* qpos = (const float*)d_in[2];
    const float* Wl   = (const float*)d_in[3];
    const float* bl   = (const float*)d_in[4];
    const float* Bm   = (const float*)d_in[5];
    const float* W1   = (const float*)d_in[6];
    const float* b1   = (const float*)d_in[7];
    const float* W2   = (const float*)d_in[8];
    const float* filt = (const float*)d_in[9];
    const float* bias = (const float*)d_in[10];
    float* out = (float*)d_out;

    cudaFuncSetAttribute(k_gA, cudaFuncAttributeMaxDynamicSharedMemorySize, GA_SMEM);
    cudaFuncSetAttribute(k_gB, cudaFuncAttributeMaxDynamicSharedMemorySize,
                         (32 * MTI + 32 * WPD) * (int)sizeof(float));

    k_w2e  <<<264, 256>>>(W2, filt);
    k_xlin <<<2048, 256>>>(x, Wl, bl);
    k_select<<<Q_N, 256>>>(pos, qpos, Bm, W1, b1);
    k_gA   <<<Q_N * 4, 256, GA_SMEM>>>();
    k_gB   <<<128, 256, (32 * MTI + 32 * WPD) * sizeof(float)>>>(bias, out);
}

// round 10
// speedup vs baseline: 2.3056x; 1.1074x over previous
#include <cuda_runtime.h>
#include <math.h>

#define C_IN   64
#define V_N    2048
#define Q_N    512
#define BT_N   8
#define KSEL   103
#define JW     33
#define M_TOT  2112          // 64 * 33
#define GST    36            // padded g row stride
#define RST    36            // reduction buffer row stride (16B-aligned)

typedef unsigned long long ull;

// ---- scratch (static device globals; no runtime allocation) ----
__device__ float d_xl [BT_N * V_N * C_IN];
__device__ float d_g  [Q_N * KSEL * JW];
__device__ int   d_ind[Q_N * KSEL];
__device__ float d_A  [BT_N * Q_N * M_TOT];    // layout: [row][j*64 + c]
__device__ float d_W2e[M_TOT * 32];            // [j*64+c][d]

// ---- f32x2 packed math ----
__device__ __forceinline__ ull fma2v(ull a, ull b, ull c) {
    ull d; asm("fma.rn.f32x2 %0, %1, %2, %3;" : "=l"(d) : "l"(a), "l"(b), "l"(c)); return d;
}
__device__ __forceinline__ ull pack2(float lo, float hi) {
    ull r; asm("mov.b64 %0, {%1, %2};" : "=l"(r) : "f"(lo), "f"(hi)); return r;
}
__device__ __forceinline__ float2 unpack2(ull v) {
    float2 r; asm("mov.b64 {%0, %1}, %2;" : "=f"(r.x), "=f"(r.y) : "l"(v)); return r;
}
__device__ __forceinline__ float wrap01(float d) {
    float t = d + 0.5f; t -= floorf(t); return t - 0.5f;
}

// ============================================================
// K_w2e
// ============================================================
__global__ void k_w2e(const float* __restrict__ W2, const float* __restrict__ filt) {
    int idx = blockIdx.x * 256 + threadIdx.x;
    if (idx < M_TOT * 32) {
        int m = idx >> 5, dd = idx & 31;
        int j = m >> 6, c = m & 63;
        d_W2e[idx] = (j < 32) ? __ldg(&W2[(c * 32 + dd) * 32 + j]) : __ldg(&filt[c * 32 + dd]);
    }
}

// ============================================================
// K0: xl = x @ W_lin^T + b
// ============================================================
__global__ void __launch_bounds__(256) k_xlin(const float* __restrict__ x,
                                              const float* __restrict__ Wl,
                                              const float* __restrict__ bl) {
    __shared__ __align__(16) float xs[512];
    __shared__ __align__(16) float ws[64 * 66];
    int tid = threadIdx.x;
    int base = blockIdx.x * 512;
    xs[tid]       = x[base + tid];
    xs[tid + 256] = x[base + 256 + tid];
    for (int i = tid; i < 4096; i += 256) { int cc = i >> 6, ii = i & 63; ws[cc * 66 + ii] = Wl[i]; }
    __syncthreads();
    int c = tid & 63, rp = tid >> 6;
    ull aA = 0, aB = 0;
    const ull* wp = (const ull*)&ws[c * 66];
    const ull* xA = (const ull*)&xs[rp * 64];
    const ull* xB = (const ull*)&xs[(rp + 4) * 64];
#pragma unroll
    for (int i2 = 0; i2 < 32; i2++) {
        ull w2_ = wp[i2];
        aA = fma2v(xA[i2], w2_, aA);
        aB = fma2v(xB[i2], w2_, aB);
    }
    float bv = __ldg(&bl[c]);
    float2 fA = unpack2(aA), fB = unpack2(aB);
    d_xl[base + rp * 64 + c]       = fA.x + fA.y + bv;
    d_xl[base + (rp + 4) * 64 + c] = fB.x + fB.y + bv;
}

// ============================================================
// K1: per query — radix-select 103 NN, softmax weights, RFF/MLP/GELU -> g
// ============================================================
__global__ void __launch_bounds__(256) k_select(const float* __restrict__ pos,
                                                const float* __restrict__ qpos,
                                                const float* __restrict__ Bmat,
                                                const float* __restrict__ W1,
                                                const float* __restrict__ b1) {
    __shared__ float e_s[V_N];
    __shared__ unsigned hist[256];
    __shared__ int   sel_i[KSEL];
    __shared__ float sel_e[KSEL];
    __shared__ float sel_w[KSEL];
    __shared__ __align__(16) float kf_s[KSEL * 32];
    __shared__ float bs[32];
    __shared__ unsigned s_kth;
    __shared__ int s_rem;
    __shared__ float s_min, s_sum;
    __shared__ int w_lt[8], w_eq[8], w_lt_off[8], w_eq_off[8];

    int q = blockIdx.x, tid = threadIdx.x, wid = tid >> 5, lane = tid & 31;
    const unsigned full = 0xffffffffu;
    unsigned ltm = (1u << lane) - 1u;
    float q0 = __ldg(&qpos[2 * q]), q1 = __ldg(&qpos[2 * q + 1]);

    ull wl[16];
#pragma unroll
    for (int t = 0; t < 16; t++) wl[t] = *(const ull*)&W1[lane * 32 + 2 * t];
    float b1r = __ldg(&b1[lane]);
    if (tid < 32) bs[tid] = __ldg(&Bmat[tid]);

    for (int v = tid; v < V_N; v += 256) {
        float d0 = wrap01(q0 - __ldg(&pos[2 * v]));
        float d1 = wrap01(q1 - __ldg(&pos[2 * v + 1]));
        e_s[v] = d0 * d0 + d1 * d1;
    }
    __syncthreads();

    unsigned prefix = 0; int remaining = KSEL;
    for (int shift = 24; shift >= 0; shift -= 8) {
        hist[tid] = 0;
        __syncthreads();
        unsigned pm = (shift == 24) ? 0u : (0xFFFFFFFFu << (shift + 8));
        for (int v = tid; v < V_N; v += 256) {
            unsigned u = __float_as_uint(e_s[v]);
            if ((u & pm) == prefix) atomicAdd(&hist[(u >> shift) & 255], 1u);
        }
        __syncthreads();
        if (tid < 32) {
            unsigned c8[8]; int lsum = 0;
#pragma unroll
            for (int j = 0; j < 8; j++) { c8[j] = hist[tid * 8 + j]; lsum += (int)c8[j]; }
            int pre = lsum;
#pragma unroll
            for (int o = 1; o < 32; o <<= 1) { int t2 = __shfl_up_sync(full, pre, o); if (lane >= o) pre += t2; }
            int excl = pre - lsum;
            if (excl < remaining && pre >= remaining) {
                int r2 = remaining - excl; int cum = 0, j = 0;
#pragma unroll
                for (j = 0; j < 8; j++) { cum += (int)c8[j]; if (cum >= r2) break; }
                s_kth = prefix | ((unsigned)(tid * 8 + j) << shift);
                s_rem = r2 - (cum - (int)c8[j]);
            }
        }
        __syncthreads();
        prefix = s_kth; remaining = s_rem;
        __syncthreads();
    }
    unsigned kth = prefix;

    {
        int nlt = 0, neq = 0;
#pragma unroll
        for (int it = 0; it < 8; it++) {
            unsigned u = __float_as_uint(e_s[wid * 256 + it * 32 + lane]);
            nlt += __popc(__ballot_sync(full, u < kth));
            neq += __popc(__ballot_sync(full, u == kth));
        }
        if (lane == 0) { w_lt[wid] = nlt; w_eq[wid] = neq; }
        __syncthreads();
        if (tid == 0) {
            int a = 0;
            for (int w = 0; w < 8; w++) { w_lt_off[w] = a; a += w_lt[w]; }
            int b2 = a;
            for (int w = 0; w < 8; w++) { w_eq_off[w] = b2; b2 += w_eq[w]; }
        }
        __syncthreads();
        int plt = w_lt_off[wid], peq = w_eq_off[wid];
#pragma unroll
        for (int it = 0; it < 8; it++) {
            int v = wid * 256 + it * 32 + lane;
            unsigned u = __float_as_uint(e_s[v]);
            bool lt = u < kth; unsigned bal = __ballot_sync(full, lt);
            if (lt) { int p = plt + __popc(bal & ltm); sel_i[p] = v; sel_e[p] = e_s[v]; }
            plt += __popc(bal);
            bool eq = (u == kth); unsigned b3 = __ballot_sync(full, eq);
            if (eq) { int p = peq + __popc(b3 & ltm); if (p < KSEL) { sel_i[p] = v; sel_e[p] = e_s[v]; } }
            peq += __popc(b3);
        }
    }
    __syncthreads();

    if (tid < 32) {
        float m = 3.0e38f;
        for (int k = lane; k < KSEL; k += 32) m = fminf(m, sel_e[k]);
        for (int o = 16; o; o >>= 1) m = fminf(m, __shfl_xor_sync(full, m, o));
        if (lane == 0) s_min = m;
    }
    __syncthreads();
    float emin = s_min;
    float emax = __uint_as_float(kth);
    float denom = (emax - emin) + 1e-8f;
    if (tid < KSEL) sel_w[tid] = expf(-((sel_e[tid] - emin) / denom));
    __syncthreads();
    if (tid < 32) {
        float s = 0.f;
        for (int k = lane; k < KSEL; k += 32) s += sel_w[k];
        for (int o = 16; o; o >>= 1) s += __shfl_xor_sync(full, s, o);
        if (lane == 0) s_sum = s;
    }
    __syncthreads();

    if (tid < KSEL) {
        float w = sel_w[tid] / s_sum;
        sel_w[tid] = w;
        int v = sel_i[tid];
        float d0 = wrap01(q0 - __ldg(&pos[2 * v]));
        float d1 = wrap01(q1 - __ldg(&pos[2 * v + 1]));
#pragma unroll
        for (int j = 0; j < 16; j++) {
            float p = 6.283185307179586f * (d0 * bs[j] + d1 * bs[16 + j]);
            float sv, cv; sincosf(p, &sv, &cv);
            kf_s[tid * 32 + j]      = sv;
            kf_s[tid * 32 + 16 + j] = cv;
        }
        d_g[(q * KSEL + tid) * JW + 32] = w;
        d_ind[q * KSEL + tid] = v;
    }
    __syncthreads();

#pragma unroll 1
    for (int rr = 0; rr < 13; rr++) {
        int k = wid + rr * 8;
        if (k < KSEL) {
            ull acc = 0;
            const ull* kp = (const ull*)&kf_s[k * 32];
#pragma unroll
            for (int t = 0; t < 16; t++) acc = fma2v(kp[t], wl[t], acc);
            float2 f = unpack2(acc);
            float a = f.x + f.y + b1r;
            float h = 0.5f * a * (1.0f + erff(a * 0.70710678118654752f));
            d_g[(q * KSEL + k) * JW + lane] = sel_w[k] * h;
        }
    }
}

// ============================================================
// K2a: block = (q, bt-pair), 256 threads.
// Thread = (kh, bt-half, t): kh splits k-range in two; 8c x 4j tile.
// j=32 (weight) column is computed DURING the gather (registers + 4KB smem
// reduction), removing the scalar aw loop from the main path.
// ============================================================
#define GA_SMEM ((KSEL * GST + 2 * KSEL * C_IN) * 4)   // 67568 B

__global__ void __launch_bounds__(256, 3) k_gA() {
    extern __shared__ __align__(16) float sm[];
    float* g_s = sm;                       // [103][36]
    float* xg0 = sm + KSEL * GST;          // [103][64] bt0
    float* xg1 = xg0 + KSEL * C_IN;        // [103][64] bt1
    __shared__ int ind_s[KSEL];
    __shared__ float wred[2][8][C_IN];     // per-bt partial w-column sums

    int bx = blockIdx.x, q = bx >> 2, btp = bx & 3;
    int tid = threadIdx.x;

    if (tid < KSEL) ind_s[tid] = d_ind[q * KSEL + tid];
    {
        const float* gsrc = &d_g[q * KSEL * JW];
        for (int i = tid; i < KSEL * JW; i += 256) {
            int k = i / 33, j = i - k * 33;
            g_s[k * GST + j] = gsrc[i];
        }
    }
    __syncthreads();

    // gather: 128 threads per bt; also accumulate w-column on the fly
    {
        int gb = tid >> 7;
        int gt = tid & 127;
        const float* xb = &d_xl[(btp * 2 + gb) * V_N * C_IN];
        float* xdst = gb ? xg1 : xg0;
        int rr = gt >> 4, c4 = (gt & 15) * 4;
        float4 wa = make_float4(0.f, 0.f, 0.f, 0.f);
#pragma unroll 4
        for (int r = rr; r < KSEL; r += 8) {
            float4 v = __ldg((const float4*)&xb[ind_s[r] * C_IN + c4]);
            *(float4*)&xdst[r * C_IN + c4] = v;
            float wr = g_s[r * GST + 32];
            wa.x += wr * v.x; wa.y += wr * v.y; wa.z += wr * v.z; wa.w += wr * v.w;
        }
        wred[gb][rr][c4]     = wa.x;
        wred[gb][rr][c4 + 1] = wa.y;
        wred[gb][rr][c4 + 2] = wa.z;
        wred[gb][rr][c4 + 3] = wa.w;
    }
    __syncthreads();

    int kh   = tid >> 7;                   // k-half: 0 -> [0,52), 1 -> [52,103)
    int half = (tid >> 6) & 1;             // bt of pair
    int t    = tid & 63;
    int cg = t & 7, jg = t >> 3;
    const float* xg = half ? xg1 : xg0;
    const float* xgp = &xg[cg * 8];
    const float* gsp = &g_s[jg * 4];
    int kbeg = kh ? 52 : 0;
    int kend = kh ? KSEL : 52;

    ull acc[4][4];
#pragma unroll
    for (int a = 0; a < 4; a++)
#pragma unroll
        for (int b = 0; b < 4; b++) acc[a][b] = 0;

#pragma unroll 2
    for (int k = kbeg; k < kend; k++) {
        ulonglong2 x0 = *(const ulonglong2*)&xgp[k * C_IN];
        ulonglong2 x1 = *(const ulonglong2*)&xgp[k * C_IN + 4];
        float4 g4 = *(const float4*)&gsp[k * GST];
        ull gp0 = pack2(g4.x, g4.x), gp1 = pack2(g4.y, g4.y);
        ull gp2 = pack2(g4.z, g4.z), gp3 = pack2(g4.w, g4.w);
        acc[0][0] = fma2v(x0.x, gp0, acc[0][0]); acc[0][1] = fma2v(x0.y, gp0, acc[0][1]);
        acc[0][2] = fma2v(x1.x, gp0, acc[0][2]); acc[0][3] = fma2v(x1.y, gp0, acc[0][3]);
        acc[1][0] = fma2v(x0.x, gp1, acc[1][0]); acc[1][1] = fma2v(x0.y, gp1, acc[1][1]);
        acc[1][2] = fma2v(x1.x, gp1, acc[1][2]); acc[1][3] = fma2v(x1.y, gp1, acc[1][3]);
        acc[2][0] = fma2v(x0.x, gp2, acc[2][0]); acc[2][1] = fma2v(x0.y, gp2, acc[2][1]);
        acc[2][2] = fma2v(x1.x, gp2, acc[2][2]); acc[2][3] = fma2v(x1.y, gp2, acc[2][3]);
        acc[3][0] = fma2v(x0.x, gp3, acc[3][0]); acc[3][1] = fma2v(x0.y, gp3, acc[3][1]);
        acc[3][2] = fma2v(x1.x, gp3, acc[3][2]); acc[3][3] = fma2v(x1.y, gp3, acc[3][3]);
    }

    __syncthreads();
    // kh==1 threads deposit partials into buffer overlaid on xg0 (stride 36)
    float* red = xg0;                      // [128][RST]
    if (kh == 1) {
        float* rp = &red[(half * 64 + t) * RST];
#pragma unroll
        for (int j2 = 0; j2 < 4; j2++) {
            *(ulonglong2*)&rp[j2 * 8]     = make_ulonglong2(acc[j2][0], acc[j2][1]);
            *(ulonglong2*)&rp[j2 * 8 + 4] = make_ulonglong2(acc[j2][2], acc[j2][3]);
        }
    }
    __syncthreads();
    if (kh == 0) {
        const float* rp = &red[(half * 64 + t) * RST];
        int row = (btp * 2 + half) * Q_N + q;
        float* Ar = &d_A[row * M_TOT];
#pragma unroll
        for (int j2 = 0; j2 < 4; j2++) {
            float2 f0 = unpack2(acc[j2][0]), f1 = unpack2(acc[j2][1]);
            float2 f2 = unpack2(acc[j2][2]), f3 = unpack2(acc[j2][3]);
            float4 p0 = *(const float4*)&rp[j2 * 8];
            float4 p1 = *(const float4*)&rp[j2 * 8 + 4];
            float4 o0 = make_float4(f0.x + p0.x, f0.y + p0.y, f1.x + p0.z, f1.y + p0.w);
            float4 o1 = make_float4(f2.x + p1.x, f2.y + p1.y, f3.x + p1.z, f3.y + p1.w);
            int off = (jg * 4 + j2) * C_IN + cg * 8;
            *(float4*)&Ar[off]     = o0;
            *(float4*)&Ar[off + 4] = o1;
        }
        // w-column from gather-phase partials
        float a0 = 0.f;
#pragma unroll
        for (int rr = 0; rr < 8; rr++) a0 += wred[half][rr][t];
        Ar[32 * C_IN + t] = a0;
    }
}

// ============================================================
// K2b: out[row,d] = sum_m A[row,m] * W2e[m,d] + bias[d]
// 256 blocks x 256 threads; 16 rows/block for full-chip wave balance.
// ============================================================
#define MTI 264
#define WPD 266
#define GB_SMEM ((16 * MTI + 32 * WPD) * 4)
__global__ void __launch_bounds__(256) k_gB(const float* __restrict__ bias,
                                            float* __restrict__ out) {
    extern __shared__ float sm2[];
    float* As = sm2;               // [16][264]
    float* Wt = sm2 + 16 * MTI;    // [32][266]
    int tid = threadIdx.x, wid = tid >> 5, lane = tid & 31;
    int r0 = blockIdx.x * 16;
    ull acc[2] = {0, 0};

    for (int t = 0; t < 8; t++) {
        int mbase = t * MTI;
#pragma unroll
        for (int rr2 = 0; rr2 < 2; rr2++) {
            int rloc = wid * 2 + rr2;
            const float* src = &d_A[(r0 + rloc) * M_TOT + mbase];
            for (int m = lane; m < MTI; m += 32) As[rloc * MTI + m] = src[m];
        }
        for (int i = tid; i < MTI * 32; i += 256) {
            int m = i >> 5, dd = i & 31;
            Wt[dd * WPD + m] = d_W2e[mbase * 32 + i];
        }
        __syncthreads();
#pragma unroll 4
        for (int mp = 0; mp < MTI / 2; mp++) {
            ull wp = *(const ull*)&Wt[lane * WPD + 2 * mp];
            acc[0] = fma2v(*(const ull*)&As[(wid * 2 + 0) * MTI + 2 * mp], wp, acc[0]);
            acc[1] = fma2v(*(const ull*)&As[(wid * 2 + 1) * MTI + 2 * mp], wp, acc[1]);
        }
        __syncthreads();
    }
    float bv = __ldg(&bias[lane]);
#pragma unroll
    for (int j = 0; j < 2; j++) {
        float2 f = unpack2(acc[j]);
        out[(r0 + wid * 2 + j) * 32 + lane] = f.x + f.y + bv;
    }
}

// ============================================================
extern "C" void kernel_launch(void* const* d_in, const int* in_sizes, int n_in,
                              void* d_out, int out_size) {
    const float* x    = (const float*)d_in[0];
    const float* pos  = (const float*)d_in[1];
    const float* qpos = (const float*)d_in[2];
    const float* Wl   = (const float*)d_in[3];
    const float* bl   = (const float*)d_in[4];
    const float* Bm   = (const float*)d_in[5];
    const float* W1   = (const float*)d_in[6];
    const float* b1   = (const float*)d_in[7];
    const float* W2   = (const float*)d_in[8];
    const float* filt = (const float*)d_in[9];
    const float* bias = (const float*)d_in[10];
    float* out = (float*)d_out;

    cudaFuncSetAttribute(k_gA, cudaFuncAttributeMaxDynamicSharedMemorySize, GA_SMEM);
    cudaFuncSetAttribute(k_gB, cudaFuncAttributeMaxDynamicSharedMemorySize, GB_SMEM);

    k_w2e  <<<264, 256>>>(W2, filt);
    k_xlin <<<2048, 256>>>(x, Wl, bl);
    k_select<<<Q_N, 256>>>(pos, qpos, Bm, W1, b1);
    k_gA   <<<Q_N * 4, 256, GA_SMEM>>>();
    k_gB   <<<256, 256, GB_SMEM>>>(bias, out);
}

// round 11
// speedup vs baseline: 2.5484x; 1.1053x over previous
#include <cuda_runtime.h>
#include <math.h>

#define C_IN   64
#define V_N    2048
#define Q_N    512
#define BT_N   8
#define KSEL   103
#define JW     33
#define M_TOT  2112          // 64 * 33
#define GST    36            // padded g row stride

typedef unsigned long long ull;

// ---- scratch (static device globals; no runtime allocation) ----
__device__ float d_xl [BT_N * V_N * C_IN];
__device__ float d_g  [Q_N * KSEL * JW];
__device__ int   d_ind[Q_N * KSEL];
__device__ float d_A  [BT_N * Q_N * M_TOT];    // layout: [row][j*64 + c]
__device__ float d_W2e[M_TOT * 32];            // [j*64+c][d]

// ---- f32x2 packed math ----
__device__ __forceinline__ ull fma2v(ull a, ull b, ull c) {
    ull d; asm("fma.rn.f32x2 %0, %1, %2, %3;" : "=l"(d) : "l"(a), "l"(b), "l"(c)); return d;
}
__device__ __forceinline__ ull pack2(float lo, float hi) {
    ull r; asm("mov.b64 %0, {%1, %2};" : "=l"(r) : "f"(lo), "f"(hi)); return r;
}
__device__ __forceinline__ float2 unpack2(ull v) {
    float2 r; asm("mov.b64 {%0, %1}, %2;" : "=f"(r.x), "=f"(r.y) : "l"(v)); return r;
}
__device__ __forceinline__ float wrap01(float d) {
    float t = d + 0.5f; t -= floorf(t); return t - 0.5f;
}

// ============================================================
// K_w2e
// ============================================================
__global__ void k_w2e(const float* __restrict__ W2, const float* __restrict__ filt) {
    int idx = blockIdx.x * 256 + threadIdx.x;
    if (idx < M_TOT * 32) {
        int m = idx >> 5, dd = idx & 31;
        int j = m >> 6, c = m & 63;
        d_W2e[idx] = (j < 32) ? __ldg(&W2[(c * 32 + dd) * 32 + j]) : __ldg(&filt[c * 32 + dd]);
    }
}

// ============================================================
// K0: xl = x @ W_lin^T + b
// ============================================================
__global__ void __launch_bounds__(256) k_xlin(const float* __restrict__ x,
                                              const float* __restrict__ Wl,
                                              const float* __restrict__ bl) {
    __shared__ __align__(16) float xs[512];
    __shared__ __align__(16) float ws[64 * 66];
    int tid = threadIdx.x;
    int base = blockIdx.x * 512;
    xs[tid]       = x[base + tid];
    xs[tid + 256] = x[base + 256 + tid];
    for (int i = tid; i < 4096; i += 256) { int cc = i >> 6, ii = i & 63; ws[cc * 66 + ii] = Wl[i]; }
    __syncthreads();
    int c = tid & 63, rp = tid >> 6;
    ull aA = 0, aB = 0;
    const ull* wp = (const ull*)&ws[c * 66];
    const ull* xA = (const ull*)&xs[rp * 64];
    const ull* xB = (const ull*)&xs[(rp + 4) * 64];
#pragma unroll
    for (int i2 = 0; i2 < 32; i2++) {
        ull w2_ = wp[i2];
        aA = fma2v(xA[i2], w2_, aA);
        aB = fma2v(xB[i2], w2_, aB);
    }
    float bv = __ldg(&bl[c]);
    float2 fA = unpack2(aA), fB = unpack2(aB);
    d_xl[base + rp * 64 + c]       = fA.x + fA.y + bv;
    d_xl[base + (rp + 4) * 64 + c] = fB.x + fB.y + bv;
}

// ============================================================
// K1: per query — radix-select 103 NN, softmax weights, RFF/MLP/GELU -> g
// ============================================================
__global__ void __launch_bounds__(256) k_select(const float* __restrict__ pos,
                                                const float* __restrict__ qpos,
                                                const float* __restrict__ Bmat,
                                                const float* __restrict__ W1,
                                                const float* __restrict__ b1) {
    __shared__ float e_s[V_N];
    __shared__ unsigned hist[256];
    __shared__ int   sel_i[KSEL];
    __shared__ float sel_e[KSEL];
    __shared__ float sel_w[KSEL];
    __shared__ __align__(16) float kf_s[KSEL * 32];
    __shared__ float bs[32];
    __shared__ unsigned s_kth;
    __shared__ int s_rem;
    __shared__ float s_min, s_sum;
    __shared__ int w_lt[8], w_eq[8], w_lt_off[8], w_eq_off[8];

    int q = blockIdx.x, tid = threadIdx.x, wid = tid >> 5, lane = tid & 31;
    const unsigned full = 0xffffffffu;
    unsigned ltm = (1u << lane) - 1u;
    float q0 = __ldg(&qpos[2 * q]), q1 = __ldg(&qpos[2 * q + 1]);

    ull wl[16];
#pragma unroll
    for (int t = 0; t < 16; t++) wl[t] = *(const ull*)&W1[lane * 32 + 2 * t];
    float b1r = __ldg(&b1[lane]);
    if (tid < 32) bs[tid] = __ldg(&Bmat[tid]);

    for (int v = tid; v < V_N; v += 256) {
        float d0 = wrap01(q0 - __ldg(&pos[2 * v]));
        float d1 = wrap01(q1 - __ldg(&pos[2 * v + 1]));
        e_s[v] = d0 * d0 + d1 * d1;
    }
    __syncthreads();

    unsigned prefix = 0; int remaining = KSEL;
    for (int shift = 24; shift >= 0; shift -= 8) {
        hist[tid] = 0;
        __syncthreads();
        unsigned pm = (shift == 24) ? 0u : (0xFFFFFFFFu << (shift + 8));
        for (int v = tid; v < V_N; v += 256) {
            unsigned u = __float_as_uint(e_s[v]);
            if ((u & pm) == prefix) atomicAdd(&hist[(u >> shift) & 255], 1u);
        }
        __syncthreads();
        if (tid < 32) {
            unsigned c8[8]; int lsum = 0;
#pragma unroll
            for (int j = 0; j < 8; j++) { c8[j] = hist[tid * 8 + j]; lsum += (int)c8[j]; }
            int pre = lsum;
#pragma unroll
            for (int o = 1; o < 32; o <<= 1) { int t2 = __shfl_up_sync(full, pre, o); if (lane >= o) pre += t2; }
            int excl = pre - lsum;
            if (excl < remaining && pre >= remaining) {
                int r2 = remaining - excl; int cum = 0, j = 0;
#pragma unroll
                for (j = 0; j < 8; j++) { cum += (int)c8[j]; if (cum >= r2) break; }
                s_kth = prefix | ((unsigned)(tid * 8 + j) << shift);
                s_rem = r2 - (cum - (int)c8[j]);
            }
        }
        __syncthreads();
        prefix = s_kth; remaining = s_rem;
        __syncthreads();
    }
    unsigned kth = prefix;

    {
        int nlt = 0, neq = 0;
#pragma unroll
        for (int it = 0; it < 8; it++) {
            unsigned u = __float_as_uint(e_s[wid * 256 + it * 32 + lane]);
            nlt += __popc(__ballot_sync(full, u < kth));
            neq += __popc(__ballot_sync(full, u == kth));
        }
        if (lane == 0) { w_lt[wid] = nlt; w_eq[wid] = neq; }
        __syncthreads();
        if (tid == 0) {
            int a = 0;
            for (int w = 0; w < 8; w++) { w_lt_off[w] = a; a += w_lt[w]; }
            int b2 = a;
            for (int w = 0; w < 8; w++) { w_eq_off[w] = b2; b2 += w_eq[w]; }
        }
        __syncthreads();
        int plt = w_lt_off[wid], peq = w_eq_off[wid];
#pragma unroll
        for (int it = 0; it < 8; it++) {
            int v = wid * 256 + it * 32 + lane;
            unsigned u = __float_as_uint(e_s[v]);
            bool lt = u < kth; unsigned bal = __ballot_sync(full, lt);
            if (lt) { int p = plt + __popc(bal & ltm); sel_i[p] = v; sel_e[p] = e_s[v]; }
            plt += __popc(bal);
            bool eq = (u == kth); unsigned b3 = __ballot_sync(full, eq);
            if (eq) { int p = peq + __popc(b3 & ltm); if (p < KSEL) { sel_i[p] = v; sel_e[p] = e_s[v]; } }
            peq += __popc(b3);
        }
    }
    __syncthreads();

    if (tid < 32) {
        float m = 3.0e38f;
        for (int k = lane; k < KSEL; k += 32) m = fminf(m, sel_e[k]);
        for (int o = 16; o; o >>= 1) m = fminf(m, __shfl_xor_sync(full, m, o));
        if (lane == 0) s_min = m;
    }
    __syncthreads();
    float emin = s_min;
    float emax = __uint_as_float(kth);
    float denom = (emax - emin) + 1e-8f;
    if (tid < KSEL) sel_w[tid] = expf(-((sel_e[tid] - emin) / denom));
    __syncthreads();
    if (tid < 32) {
        float s = 0.f;
        for (int k = lane; k < KSEL; k += 32) s += sel_w[k];
        for (int o = 16; o; o >>= 1) s += __shfl_xor_sync(full, s, o);
        if (lane == 0) s_sum = s;
    }
    __syncthreads();

    if (tid < KSEL) {
        float w = sel_w[tid] / s_sum;
        sel_w[tid] = w;
        int v = sel_i[tid];
        float d0 = wrap01(q0 - __ldg(&pos[2 * v]));
        float d1 = wrap01(q1 - __ldg(&pos[2 * v + 1]));
#pragma unroll
        for (int j = 0; j < 16; j++) {
            float p = 6.283185307179586f * (d0 * bs[j] + d1 * bs[16 + j]);
            float sv, cv; sincosf(p, &sv, &cv);
            kf_s[tid * 32 + j]      = sv;
            kf_s[tid * 32 + 16 + j] = cv;
        }
        d_g[(q * KSEL + tid) * JW + 32] = w;
        d_ind[q * KSEL + tid] = v;
    }
    __syncthreads();

#pragma unroll 1
    for (int rr = 0; rr < 13; rr++) {
        int k = wid + rr * 8;
        if (k < KSEL) {
            ull acc = 0;
            const ull* kp = (const ull*)&kf_s[k * 32];
#pragma unroll
            for (int t = 0; t < 16; t++) acc = fma2v(kp[t], wl[t], acc);
            float2 f = unpack2(acc);
            float a = f.x + f.y + b1r;
            float h = 0.5f * a * (1.0f + erff(a * 0.70710678118654752f));
            d_g[(q * KSEL + k) * JW + lane] = sel_w[k] * h;
        }
    }
}

// ============================================================
// K2a: block = (q, bt), 256 threads, 2-way k-split, thread tile 4c x 4j.
// 41.2 KB dyn smem -> 5 blocks/SM (occ ~62%). w-column folded into gather.
// ============================================================
#define GA_SMEM ((KSEL * GST + KSEL * C_IN) * 4)   // 41200 B

__global__ void __launch_bounds__(256, 5) k_gA() {
    extern __shared__ __align__(16) float sm[];
    float* g_s = sm;                  // [103][36]
    float* xg  = sm + KSEL * GST;     // [103][64]; tail reused as reduction buf
    __shared__ int ind_s[KSEL];
    __shared__ float wred[8][C_IN];

    int bx = blockIdx.x, q = bx >> 3, bt = bx & 7;
    int tid = threadIdx.x;

    if (tid < KSEL) ind_s[tid] = d_ind[q * KSEL + tid];
    {
        const float* gsrc = &d_g[q * KSEL * JW];
        for (int i = tid; i < KSEL * JW; i += 256) {
            int k = i / 33, j = i - k * 33;
            g_s[k * GST + j] = gsrc[i];
        }
    }
    __syncthreads();

    // gather: warp w loads rows w, w+8, ...; float2 per lane; w-column on the fly
    {
        int w = tid >> 5, lane = tid & 31;
        const float* xb = &d_xl[bt * V_N * C_IN];
        float2 wa = make_float2(0.f, 0.f);
        for (int r = w; r < KSEL; r += 8) {
            float2 v = __ldg((const float2*)&xb[ind_s[r] * C_IN + lane * 2]);
            *(float2*)&xg[r * C_IN + lane * 2] = v;
            float wr = g_s[r * GST + 32];
            wa.x += wr * v.x; wa.y += wr * v.y;
        }
        wred[w][lane * 2]     = wa.x;
        wred[w][lane * 2 + 1] = wa.y;
    }
    __syncthreads();

    int kh = tid >> 7;                 // k-half: 0 -> [0,52), 1 -> [52,103)
    int t  = tid & 127;
    int cg = t & 15, jg = t >> 4;      // 16 c-groups of 4; 8 j-groups of 4
    const float* xgp = &xg[cg * 4];
    const float* gsp = &g_s[jg * 4];
    int kbeg = kh ? 52 : 0;
    int kend = kh ? KSEL : 52;

    ull acc[4][2];
#pragma unroll
    for (int a = 0; a < 4; a++) { acc[a][0] = 0; acc[a][1] = 0; }

#pragma unroll 2
    for (int k = kbeg; k < kend; k++) {
        ulonglong2 x0 = *(const ulonglong2*)&xgp[k * C_IN];
        float4 g4 = *(const float4*)&gsp[k * GST];
        ull gp0 = pack2(g4.x, g4.x), gp1 = pack2(g4.y, g4.y);
        ull gp2 = pack2(g4.z, g4.z), gp3 = pack2(g4.w, g4.w);
        acc[0][0] = fma2v(x0.x, gp0, acc[0][0]); acc[0][1] = fma2v(x0.y, gp0, acc[0][1]);
        acc[1][0] = fma2v(x0.x, gp1, acc[1][0]); acc[1][1] = fma2v(x0.y, gp1, acc[1][1]);
        acc[2][0] = fma2v(x0.x, gp2, acc[2][0]); acc[2][1] = fma2v(x0.y, gp2, acc[2][1]);
        acc[3][0] = fma2v(x0.x, gp3, acc[3][0]); acc[3][1] = fma2v(x0.y, gp3, acc[3][1]);
    }

    __syncthreads();
    // kh==1 deposits partials into buffer overlaid on xg (stride 20 floats = 80B, 16B-aligned)
    float* red = xg;                   // [128][20]
    if (kh == 1) {
        float* rp = &red[t * 20];
#pragma unroll
        for (int j2 = 0; j2 < 4; j2++)
            *(ulonglong2*)&rp[j2 * 4] = make_ulonglong2(acc[j2][0], acc[j2][1]);
    }
    __syncthreads();
    if (kh == 0) {
        const float* rp = &red[t * 20];
        int row = bt * Q_N + q;
        float* Ar = &d_A[row * M_TOT];
#pragma unroll
        for (int j2 = 0; j2 < 4; j2++) {
            float2 f0 = unpack2(acc[j2][0]), f1 = unpack2(acc[j2][1]);
            float4 p = *(const float4*)&rp[j2 * 4];
            *(float4*)&Ar[(jg * 4 + j2) * C_IN + cg * 4] =
                make_float4(f0.x + p.x, f0.y + p.y, f1.x + p.z, f1.y + p.w);
        }
        if (t < C_IN) {
            float a0 = 0.f;
#pragma unroll
            for (int rr = 0; rr < 8; rr++) a0 += wred[rr][t];
            Ar[32 * C_IN + t] = a0;
        }
    }
}

// ============================================================
// K2b: out[row,d] = sum_m A[row,m] * W2e[m,d] + bias[d]
// 256 blocks x 256 threads; 16 rows/block.
// ============================================================
#define MTI 264
#define WPD 266
#define GB_SMEM ((16 * MTI + 32 * WPD) * 4)
__global__ void __launch_bounds__(256) k_gB(const float* __restrict__ bias,
                                            float* __restrict__ out) {
    extern __shared__ float sm2[];
    float* As = sm2;               // [16][264]
    float* Wt = sm2 + 16 * MTI;    // [32][266]
    int tid = threadIdx.x, wid = tid >> 5, lane = tid & 31;
    int r0 = blockIdx.x * 16;
    ull acc[2] = {0, 0};

    for (int t = 0; t < 8; t++) {
        int mbase = t * MTI;
#pragma unroll
        for (int rr2 = 0; rr2 < 2; rr2++) {
            int rloc = wid * 2 + rr2;
            const float* src = &d_A[(r0 + rloc) * M_TOT + mbase];
            for (int m = lane; m < MTI; m += 32) As[rloc * MTI + m] = src[m];
        }
        for (int i = tid; i < MTI * 32; i += 256) {
            int m = i >> 5, dd = i & 31;
            Wt[dd * WPD + m] = d_W2e[mbase * 32 + i];
        }
        __syncthreads();
#pragma unroll 4
        for (int mp = 0; mp < MTI / 2; mp++) {
            ull wp = *(const ull*)&Wt[lane * WPD + 2 * mp];
            acc[0] = fma2v(*(const ull*)&As[(wid * 2 + 0) * MTI + 2 * mp], wp, acc[0]);
            acc[1] = fma2v(*(const ull*)&As[(wid * 2 + 1) * MTI + 2 * mp], wp, acc[1]);
        }
        __syncthreads();
    }
    float bv = __ldg(&bias[lane]);
#pragma unroll
    for (int j = 0; j < 2; j++) {
        float2 f = unpack2(acc[j]);
        out[(r0 + wid * 2 + j) * 32 + lane] = f.x + f.y + bv;
    }
}

// ============================================================
extern "C" void kernel_launch(void* const* d_in, const int* in_sizes, int n_in,
                              void* d_out, int out_size) {
    const float* x    = (const float*)d_in[0];
    const float* pos  = (const float*)d_in[1];
    const float* qpos = (const float*)d_in[2];
    const float* Wl   = (const float*)d_in[3];
    const float* bl   = (const float*)d_in[4];
    const float* Bm   = (const float*)d_in[5];
    const float* W1   = (const float*)d_in[6];
    const float* b1   = (const float*)d_in[7];
    const float* W2   = (const float*)d_in[8];
    const float* filt = (const float*)d_in[9];
    const float* bias = (const float*)d_in[10];
    float* out = (float*)d_out;

    cudaFuncSetAttribute(k_gA, cudaFuncAttributeMaxDynamicSharedMemorySize, GA_SMEM);
    cudaFuncSetAttribute(k_gB, cudaFuncAttributeMaxDynamicSharedMemorySize, GB_SMEM);

    k_w2e  <<<264, 256>>>(W2, filt);
    k_xlin <<<2048, 256>>>(x, Wl, bl);
    k_select<<<Q_N, 256>>>(pos, qpos, Bm, W1, b1);
    k_gA   <<<Q_N * BT_N, 256, GA_SMEM>>>();
    k_gB   <<<256, 256, GB_SMEM>>>(bias, out);
}